// round 13
// baseline (speedup 1.0000x reference)
#include <cuda_runtime.h>
#include <cuda_bf16.h>
#include <cstdint>
#include <math.h>

// ---------------------------------------------------------------------------
// CARAFE fp32.  Round 13: conv3mma double-buffered cp.async pipeline
// (stage chunk c+1 overlaps mma on chunk c); k_act back to 256 blocks.
// ---------------------------------------------------------------------------

#define B 8
#define CIN 128
#define MID 64
#define OC2 100
#define HW 4096
#define EPS 1e-5f

typedef unsigned long long u64;
typedef unsigned short u16;

__device__ __forceinline__ u64 pk(float lo, float hi) {
    u64 r; asm("mov.b64 %0,{%1,%2};" : "=l"(r) : "f"(lo), "f"(hi)); return r;
}
__device__ __forceinline__ void fma2(u64& d, u64 a, u64 b) {
    asm("fma.rn.f32x2 %0,%1,%2,%0;" : "+l"(d) : "l"(a), "l"(b));
}
__device__ __forceinline__ u64 add2(u64 a, u64 b) {
    u64 r; asm("add.rn.f32x2 %0,%1,%2;" : "=l"(r) : "l"(a), "l"(b)); return r;
}
__device__ __forceinline__ void unpk(u64 a, float& lo, float& hi) {
    asm("mov.b64 {%0,%1},%2;" : "=f"(lo), "=f"(hi) : "l"(a));
}
__device__ __forceinline__ u16 bfbits(float v) {
    __nv_bfloat16 h = __float2bfloat16(v);
    return *reinterpret_cast<u16*>(&h);
}
__device__ __forceinline__ float bf2f(u16 s) {
    __nv_bfloat16 h = *reinterpret_cast<__nv_bfloat16*>(&s);
    return __bfloat162float(h);
}
__device__ __forceinline__ uint32_t smem_u32(const void* p) {
    uint32_t a;
    asm("{ .reg .u64 t; cvta.to.shared.u64 t, %1; cvt.u32.u64 %0, t; }"
        : "=r"(a) : "l"(p));
    return a;
}

// mma.sync m16n8k16 row.col f32.bf16.bf16.f32
__device__ __forceinline__ void mmabf(float& d0, float& d1, float& d2, float& d3,
                                      uint32_t a0, uint32_t a1, uint32_t a2, uint32_t a3,
                                      uint32_t b0, uint32_t b1) {
    asm volatile(
        "mma.sync.aligned.m16n8k16.row.col.f32.bf16.bf16.f32 "
        "{%0,%1,%2,%3},{%4,%5,%6,%7},{%8,%9},{%0,%1,%2,%3};"
        : "+f"(d0), "+f"(d1), "+f"(d2), "+f"(d3)
        : "r"(a0), "r"(a1), "r"(a2), "r"(a3), "r"(b0), "r"(b1));
}
__device__ __forceinline__ void lm4(uint32_t& r0, uint32_t& r1, uint32_t& r2,
                                    uint32_t& r3, uint32_t a) {
    asm volatile("ldmatrix.sync.aligned.m8n8.x4.shared.b16 {%0,%1,%2,%3},[%4];"
                 : "=r"(r0), "=r"(r1), "=r"(r2), "=r"(r3) : "r"(a));
}
__device__ __forceinline__ void lm2(uint32_t& r0, uint32_t& r1, uint32_t a) {
    asm volatile("ldmatrix.sync.aligned.m8n8.x2.shared.b16 {%0,%1},[%2];"
                 : "=r"(r0), "=r"(r1) : "r"(a));
}
__device__ __forceinline__ void cpasync16(uint32_t dst, const void* src, int srcsize) {
    asm volatile("cp.async.cg.shared.global [%0], [%1], 16, %2;"
                 :: "r"(dst), "l"(src), "r"(srcsize) : "memory");
}
#define CP_COMMIT() asm volatile("cp.async.commit_group;" ::: "memory")
#define CP_WAIT(n)  asm volatile("cp.async.wait_group %0;" :: "n"(n) : "memory")

// scratch
__device__ __align__(16) float g_t1[B * MID * HW];
__device__ __align__(16) float g_t2[B * OC2 * HW];
__device__ float g_sc2[OC2], g_sh2[OC2];
__device__ __align__(16) float g_p1s[128 * 64], g_p1q[128 * 64];
__device__ __align__(16) float g_p2s[256 * 100], g_p2q[256 * 100];
__device__ __align__(16) float g_w1T[128 * 64];                 // [cc][oc]
__device__ __align__(16) u16 g_aH[B * HW * 64], g_aL[B * HW * 64];  // [b][px][c]
__device__ __align__(16) u16 g_wH[18 * 4096], g_wL[18 * 4096];  // [chunk][oc 128][k 32]

__device__ __forceinline__ void wred2(u64& s, u64& q) {
#pragma unroll
    for (int o = 16; o; o >>= 1) {
        s = add2(s, __shfl_down_sync(0xFFFFFFFFu, s, o));
        q = add2(q, __shfl_down_sync(0xFFFFFFFFu, q, o));
    }
}

// ---------------------------------------------------------------------------
// prep
// ---------------------------------------------------------------------------
__global__ void k_prep(const float* __restrict__ cw, const float* __restrict__ ew) {
    int idx = blockIdx.x * 256 + threadIdx.x;
    if (idx < 18 * 4096) {
        int chunk = idx >> 12;
        int r = idx & 4095;
        int oc = r >> 5, k = r & 31;
        int tap = chunk >> 1, half = chunk & 1;
        float v = 0.f;
        if (oc < 100) v = ew[(oc * 64 + half * 32 + k) * 9 + tap];
        u16 hb = bfbits(v);
        float hf = bf2f(hb);
        g_wH[idx] = hb;
        g_wL[idx] = bfbits(v - hf);
    } else if (idx < 18 * 4096 + 8192) {
        int j = idx - 18 * 4096;
        int cc = j >> 6, oc = j & 63;
        g_w1T[j] = cw[oc * 128 + cc];
    }
}

// ---------------------------------------------------------------------------
// conv1x1: grid(16,8) x 256.  thread: 4 px x 8 oc-pairs. + BN partials.
// ---------------------------------------------------------------------------
__global__ void k_conv1(const float* __restrict__ x) {
    __shared__ float xs[32][256];
    __shared__ __align__(16) float ws1[32][64];
    __shared__ u64 r_s[8][8], r_q[8][8];
    const int b = blockIdx.y;
    const int p0 = blockIdx.x * 256;
    const int tid = threadIdx.x;
    const int pixg = tid & 63;
    const int ocg = tid >> 6;

    u64 acc[8][4];
#pragma unroll
    for (int p = 0; p < 8; p++)
#pragma unroll
        for (int j = 0; j < 4; j++) acc[p][j] = 0ull;

    for (int c0 = 0; c0 < CIN; c0 += 32) {
        __syncthreads();
#pragma unroll 4
        for (int j = 0; j < 32; j++)
            xs[j][tid] = x[((size_t)(b * CIN + c0 + j) << 12) + p0 + tid];
#pragma unroll
        for (int j = 0; j < 8; j++) {
            int idx = j * 256 + tid;
            int oc = idx & 63, cc = idx >> 6;
            ws1[cc][oc] = g_w1T[(c0 + cc) * 64 + oc];
        }
        __syncthreads();
#pragma unroll 4
        for (int cc = 0; cc < 32; cc++) {
            float4 xv = *(const float4*)&xs[cc][pixg * 4];
            u64 P0 = pk(xv.x, xv.x), P1 = pk(xv.y, xv.y);
            u64 P2 = pk(xv.z, xv.z), P3 = pk(xv.w, xv.w);
            const u64* wp = (const u64*)&ws1[cc][ocg * 16];
#pragma unroll
            for (int p = 0; p < 8; p++) {
                u64 w = wp[p];
                fma2(acc[p][0], w, P0);
                fma2(acc[p][1], w, P1);
                fma2(acc[p][2], w, P2);
                fma2(acc[p][3], w, P3);
            }
        }
    }
    const int lane = tid & 31, wid = tid >> 5;
#pragma unroll
    for (int p = 0; p < 8; p++) {
        int oce = ocg * 16 + 2 * p;
        float e0, o0, e1, o1, e2, o2, e3, o3;
        unpk(acc[p][0], e0, o0); unpk(acc[p][1], e1, o1);
        unpk(acc[p][2], e2, o2); unpk(acc[p][3], e3, o3);
        *(float4*)&g_t1[((size_t)(b * MID + oce) << 12) + p0 + pixg * 4] =
            make_float4(e0, e1, e2, e3);
        *(float4*)&g_t1[((size_t)(b * MID + oce + 1) << 12) + p0 + pixg * 4] =
            make_float4(o0, o1, o2, o3);
        u64 s = add2(add2(acc[p][0], acc[p][1]), add2(acc[p][2], acc[p][3]));
        u64 q = 0ull;
        fma2(q, acc[p][0], acc[p][0]); fma2(q, acc[p][1], acc[p][1]);
        fma2(q, acc[p][2], acc[p][2]); fma2(q, acc[p][3], acc[p][3]);
        wred2(s, q);
        if (lane == 0) { r_s[wid][p] = s; r_q[wid][p] = q; }
    }
    __syncthreads();
    if (tid < 32) {
        int g = tid >> 3, p = tid & 7;
        u64 s = add2(r_s[2 * g][p], r_s[2 * g + 1][p]);
        u64 q = add2(r_q[2 * g][p], r_q[2 * g + 1][p]);
        int blk = b * 16 + blockIdx.x;
        *(u64*)&g_p1s[blk * 64 + 2 * (g * 8 + p)] = s;
        *(u64*)&g_p1q[blk * 64 + 2 * (g * 8 + p)] = q;
    }
}

// ---------------------------------------------------------------------------
// act (fin1 fused): grid(32,8) x 256; block = 2 rows.
// ---------------------------------------------------------------------------
__global__ void k_act(const float* __restrict__ gam, const float* __restrict__ bet) {
    __shared__ float ts[64][65];
    __shared__ float ps[4][64], pq[4][64];
    __shared__ float sc[64], sh[64];
    const int y0 = blockIdx.x * 2, b = blockIdx.y;
    const int tid = threadIdx.x;

    {   // fused BN1 finalize (once per block)
        int c = tid & 63, gp = tid >> 6;
        float s = 0.f, q = 0.f;
#pragma unroll 8
        for (int i = 0; i < 32; i++) {
            int blk = gp * 32 + i;
            s += g_p1s[blk * 64 + c];
            q += g_p1q[blk * 64 + c];
        }
        ps[gp][c] = s; pq[gp][c] = q;
    }
    __syncthreads();
    if (tid < 64) {
        float s = ps[0][tid] + ps[1][tid] + ps[2][tid] + ps[3][tid];
        float q = pq[0][tid] + pq[1][tid] + pq[2][tid] + pq[3][tid];
        const float inv = 1.f / 32768.f;
        float m = s * inv, var = fmaf(-m, m, q * inv);
        float k = gam[tid] * rsqrtf(var + EPS);
        sc[tid] = k; sh[tid] = bet[tid] - m * k;
    }

#pragma unroll 1
    for (int ry = 0; ry < 2; ry++) {
        const int y = y0 + ry;
        __syncthreads();
#pragma unroll
        for (int it = 0; it < 4; it++) {
            int idx = it * 256 + tid;          // over 1024 float4
            int c = idx >> 4, x4 = idx & 15;
            float4 v = *(const float4*)&g_t1[((size_t)(b * MID + c) << 12)
                                             + (y << 6) + x4 * 4];
            float z0 = fmaf(v.x, sc[c], sh[c]);
            float z1 = fmaf(v.y, sc[c], sh[c]);
            float z2 = fmaf(v.z, sc[c], sh[c]);
            float z3 = fmaf(v.w, sc[c], sh[c]);
            ts[c][x4 * 4 + 0] = z0 * (1.f / (1.f + __expf(-z0)));
            ts[c][x4 * 4 + 1] = z1 * (1.f / (1.f + __expf(-z1)));
            ts[c][x4 * 4 + 2] = z2 * (1.f / (1.f + __expf(-z2)));
            ts[c][x4 * 4 + 3] = z3 * (1.f / (1.f + __expf(-z3)));
        }
        __syncthreads();
        const size_t rowbase = (size_t)((b << 6) + y) << 12;   // u16 units
        uint32_t* dH = (uint32_t*)(g_aH + rowbase);
        uint32_t* dL = (uint32_t*)(g_aL + rowbase);
#pragma unroll
        for (int it = 0; it < 8; it++) {
            int idx = it * 256 + tid;          // over 2048 c-pairs
            int xx = idx >> 5, cp = idx & 31;
            float v0 = ts[2 * cp][xx], v1 = ts[2 * cp + 1][xx];
            u16 h0 = bfbits(v0), h1 = bfbits(v1);
            u16 l0 = bfbits(v0 - bf2f(h0)), l1 = bfbits(v1 - bf2f(h1));
            dH[xx * 32 + cp] = (uint32_t)h0 | ((uint32_t)h1 << 16);
            dL[xx * 32 + cp] = (uint32_t)l0 | ((uint32_t)l1 << 16);
        }
    }
}

// ---------------------------------------------------------------------------
// conv3 via mma.sync bf16x3 + ldmatrix + cp.async double buffer.
// grid(32,8) x 256.  buffer = 40960B: AH/AL@0/10240, BH/BL@20480/30720.
// ---------------------------------------------------------------------------
#define C3_SMEM 81920

__device__ __forceinline__ void stage_chunk(uint32_t sbuf, int chunk, int tile,
                                            int b, int tid) {
    const int tap = chunk >> 1, half = chunk & 1;
    const int dy = tap / 3 - 1, dx = tap - (tap / 3) * 3 - 1;
#pragma unroll
    for (int it = 0; it < 8; it++) {
        int idx = it * 256 + tid;
        if (idx < 1024) {
            int arr = idx >> 9, j = idx & 511;
            int pxl = j >> 2, u = j & 3;
            int gy = tile * 2 + (pxl >> 6) + dy;
            int gx = (pxl & 63) + dx;
            bool ok = ((unsigned)gy < 64u) && ((unsigned)gx < 64u);
            int gyc = ok ? gy : 0, gxc = ok ? gx : 0;
            const u16* src = (arr ? g_aL : g_aH) +
                ((size_t)(b << 12) + (gyc << 6) + gxc) * 64 + half * 32 + u * 8;
            cpasync16(sbuf + arr * 10240 + pxl * 80 + u * 16, src, ok ? 16 : 0);
        } else {
            int j = idx - 1024;
            int arr = j >> 9, jb = j & 511;
            int oc = jb >> 2, u = jb & 3;
            const u16* src = (arr ? g_wL : g_wH) + (chunk << 12) + oc * 32 + u * 8;
            cpasync16(sbuf + 20480 + arr * 10240 + oc * 80 + u * 16, src, 16);
        }
    }
}

__global__ __launch_bounds__(256) void k_conv3mma() {
    extern __shared__ __align__(16) char smc[];
    __shared__ float sAcc[128], qAcc[128];
    const uint32_t sb = smem_u32(smc);
    const int tid = threadIdx.x;
    const int tile = blockIdx.x, b = blockIdx.y;
    const int p0 = tile * 128;
    const int lane = tid & 31, wid = tid >> 5;
    const int g = lane >> 2, tg = lane & 3;
    const int wm = wid >> 1, wn = wid & 1;
    const int m0 = wm * 32, n0 = wn * 64;

    if (tid < 128) { sAcc[tid] = 0.f; qAcc[tid] = 0.f; }

    float acc[2][8][4];
#pragma unroll
    for (int mt = 0; mt < 2; mt++)
#pragma unroll
        for (int nt = 0; nt < 8; nt++)
#pragma unroll
            for (int j = 0; j < 4; j++) acc[mt][nt][j] = 0.f;

    const uint32_t aAddr = sb + (uint32_t)(m0 + (lane & 15)) * 80 + (lane >> 4) * 16;
    const uint32_t bAddr = sb + 20480u + (uint32_t)(n0 + (lane & 7)) * 80 +
                           ((lane >> 3) & 3) * 16;

    stage_chunk(sb, 0, tile, b, tid);
    CP_COMMIT();

#pragma unroll 1
    for (int chunk = 0; chunk < 18; chunk++) {
        const uint32_t bo = (chunk & 1) ? 40960u : 0u;
        if (chunk < 17) {
            stage_chunk(sb + (((chunk + 1) & 1) ? 40960u : 0u), chunk + 1, tile, b, tid);
            CP_COMMIT();
            CP_WAIT(1);
        } else {
            CP_WAIT(0);
        }
        __syncthreads();

#pragma unroll
        for (int ks = 0; ks < 2; ks++) {
            const uint32_t ko = ks * 32;
            uint32_t aH[2][4], aL[2][4];
#pragma unroll
            for (int mt = 0; mt < 2; mt++) {
                uint32_t a = aAddr + bo + mt * (16 * 80) + ko;
                lm4(aH[mt][0], aH[mt][1], aH[mt][2], aH[mt][3], a);
                lm4(aL[mt][0], aL[mt][1], aL[mt][2], aL[mt][3], a + 10240);
            }
#pragma unroll
            for (int nt = 0; nt < 8; nt++) {
                uint32_t ba = bAddr + bo + nt * (8 * 80) + ko;
                uint32_t bH0, bH1, bL0, bL1;
                lm2(bH0, bH1, ba);
                lm2(bL0, bL1, ba + 10240);
#pragma unroll
                for (int mt = 0; mt < 2; mt++) {
                    float* d = acc[mt][nt];
                    mmabf(d[0], d[1], d[2], d[3],
                          aH[mt][0], aH[mt][1], aH[mt][2], aH[mt][3], bH0, bH1);
                    mmabf(d[0], d[1], d[2], d[3],
                          aH[mt][0], aH[mt][1], aH[mt][2], aH[mt][3], bL0, bL1);
                    mmabf(d[0], d[1], d[2], d[3],
                          aL[mt][0], aL[mt][1], aL[mt][2], aL[mt][3], bH0, bH1);
                }
            }
        }
        __syncthreads();   // all warps done reading buf before restage next iter
    }

    // epilogue: store + BN2 partials
#pragma unroll
    for (int mt = 0; mt < 2; mt++) {
#pragma unroll
        for (int nt = 0; nt < 8; nt++) {
            int oc0 = n0 + nt * 8 + 2 * tg;
            int pxl = m0 + mt * 16 + g;
            float c0 = acc[mt][nt][0], c1 = acc[mt][nt][1];
            float c2 = acc[mt][nt][2], c3 = acc[mt][nt][3];
            if (oc0 < 100) {
                size_t ob = ((size_t)(b * OC2 + oc0) << 12) + p0 + pxl;
                g_t2[ob] = c0;
                g_t2[ob + 8] = c2;
                if (oc0 + 1 < 100) {
                    g_t2[ob + HW] = c1;
                    g_t2[ob + HW + 8] = c3;
                }
            }
            float s0 = c0 + c2, q0 = fmaf(c0, c0, c2 * c2);
            float s1 = c1 + c3, q1 = fmaf(c1, c1, c3 * c3);
#pragma unroll
            for (int o = 16; o >= 4; o >>= 1) {
                s0 += __shfl_down_sync(0xFFFFFFFFu, s0, o);
                q0 += __shfl_down_sync(0xFFFFFFFFu, q0, o);
                s1 += __shfl_down_sync(0xFFFFFFFFu, s1, o);
                q1 += __shfl_down_sync(0xFFFFFFFFu, q1, o);
            }
            if (lane < 4 && oc0 < 100) {
                atomicAdd(&sAcc[oc0], s0);
                atomicAdd(&qAcc[oc0], q0);
                if (oc0 + 1 < 100) {
                    atomicAdd(&sAcc[oc0 + 1], s1);
                    atomicAdd(&qAcc[oc0 + 1], q1);
                }
            }
        }
    }
    __syncthreads();
    if (tid < 100) {
        int blk = b * 32 + tile;
        g_p2s[blk * 100 + tid] = sAcc[tid];
        g_p2q[blk * 100 + tid] = qAcc[tid];
    }
}

__global__ void k_fin2(const float* __restrict__ gam, const float* __restrict__ bet) {
    const int oc = blockIdx.x, t = threadIdx.x;   // 256 threads
    float s = g_p2s[t * 100 + oc], q = g_p2q[t * 100 + oc];
#pragma unroll
    for (int o = 16; o; o >>= 1) {
        s += __shfl_down_sync(0xFFFFFFFFu, s, o);
        q += __shfl_down_sync(0xFFFFFFFFu, q, o);
    }
    __shared__ float ss[8], qq[8];
    if ((t & 31) == 0) { ss[t >> 5] = s; qq[t >> 5] = q; }
    __syncthreads();
    if (t == 0) {
        s = 0.f; q = 0.f;
#pragma unroll
        for (int i = 0; i < 8; i++) { s += ss[i]; q += qq[i]; }
        const float inv = 1.f / 32768.f;
        float m = s * inv, var = fmaf(-m, m, q * inv);
        float k = gam[oc] * rsqrtf(var + EPS);
        g_sc2[oc] = k; g_sh2[oc] = bet[oc] - m * k;
    }
}

// ---------------------------------------------------------------------------
// reassembly (unchanged)
// ---------------------------------------------------------------------------
#define RPOS 140
#define REASM_SMEM ((144 * RPOS + 256 * 25) * 4)

__global__ __launch_bounds__(256, 2) void k_reasm(const float* __restrict__ x,
                                                  float* __restrict__ out) {
    extern __shared__ float sm[];
    float* srcs = sm;
    float* wgt = sm + 144 * RPOS;

    const int b = blockIdx.y;
    const int ti0 = (blockIdx.x >> 3) << 4;
    const int tj0 = (blockIdx.x & 7) << 4;
    const int tid = threadIdx.x;
    const int sy0 = (ti0 >> 1) - 2;
    const int sx0 = (tj0 >> 1) - 2;

#pragma unroll 4
    for (int it = 0; it < 72; it++) {
        int idx = tid + it * 256;
        int c = idx / 144;
        int pos = idx - c * 144;
        int yy = pos / 12;
        int xx = pos - yy * 12;
        int gy = sy0 + yy, gx = sx0 + xx;
        float v = 0.f;
        if ((unsigned)gy < 64u && (unsigned)gx < 64u)
            v = x[((size_t)(b * CIN + c) << 12) + (gy << 6) + gx];
        int p = c >> 1;
        srcs[pos * RPOS + (p >> 4) * 36 + (p & 15) * 2 + (c & 1)] = v;
    }

    {
        int py = tid >> 4, px = tid & 15;
        int gi = ti0 + py, gj = tj0 + px;
        int y0 = gi >> 1, x0 = gj >> 1;
        int sub = ((gi & 1) << 1) | (gj & 1);
        float l[25];
        float mx = -1e30f;
#pragma unroll
        for (int k = 0; k < 25; k++) {
            int ch = (k << 2) + sub;
            float v = fmaf(g_t2[((size_t)(b * OC2 + ch) << 12) + (y0 << 6) + x0],
                           g_sc2[ch], g_sh2[ch]);
            l[k] = v;
            mx = fmaxf(mx, v);
        }
        float s = 0.f;
#pragma unroll
        for (int k = 0; k < 25; k++) { l[k] = __expf(l[k] - mx); s += l[k]; }
        float inv = 1.f / s;
#pragma unroll
        for (int k = 0; k < 25; k++) wgt[tid * 25 + k] = l[k] * inv;
    }
    __syncthreads();

    const int s4 = tid & 3;
    const int quad = tid >> 2;
    const int qy = quad >> 3, qx = quad & 7;
    const int posb = qy * 12 + qx;
    const float* wp0 = &wgt[(2 * qy * 16 + 2 * qx) * 25];
    const int gi0 = ti0 + 2 * qy;
    const int gj = tj0 + 2 * qx;

#pragma unroll 1
    for (int g = 0; g < 2; g++) {
        u64 a[2][2][8];
#pragma unroll
        for (int di = 0; di < 2; di++)
#pragma unroll
            for (int dj = 0; dj < 2; dj++)
#pragma unroll
                for (int j = 0; j < 8; j++) a[di][dj][j] = 0ull;

#pragma unroll 1
        for (int dy = 0; dy < 5; dy++) {
#pragma unroll
            for (int dx = 0; dx < 5; dx++) {
                int k = dy * 5 + dx;
                float w00 = wp0[k], w01 = wp0[25 + k];
                float w10 = wp0[400 + k], w11 = wp0[425 + k];
                u64 W00 = pk(w00, w00), W01 = pk(w01, w01);
                u64 W10 = pk(w10, w10), W11 = pk(w11, w11);
                const ulonglong2* r = (const ulonglong2*)(
                    srcs + (posb + dy * 12 + dx) * RPOS + s4 * 36 + g * 16);
                ulonglong2 q0 = r[0], q1 = r[1], q2 = r[2], q3 = r[3];
                u64 sv[8] = {q0.x, q0.y, q1.x, q1.y, q2.x, q2.y, q3.x, q3.y};
#pragma unroll
                for (int j = 0; j < 8; j++) {
                    fma2(a[0][0][j], W00, sv[j]);
                    fma2(a[0][1][j], W01, sv[j]);
                    fma2(a[1][0][j], W10, sv[j]);
                    fma2(a[1][1][j], W11, sv[j]);
                }
            }
        }

#pragma unroll
        for (int j = 0; j < 8; j++) {
            int p = s4 * 16 + g * 8 + j;
            int c = 2 * p;
#pragma unroll
            for (int di = 0; di < 2; di++) {
                float e0, h0, e1, h1;
                unpk(a[di][0][j], e0, h0);
                unpk(a[di][1][j], e1, h1);
                size_t ob = (((size_t)(b * CIN + c) << 7) + gi0 + di) * 128 + gj;
                *(float2*)&out[ob] = make_float2(e0, e1);
                *(float2*)&out[ob + 16384] = make_float2(h0, h1);
            }
        }
    }
}

// ---------------------------------------------------------------------------
extern "C" void kernel_launch(void* const* d_in, const int* in_sizes, int n_in,
                              void* d_out, int out_size) {
    const float* x      = (const float*)d_in[0];
    const float* comp_w = (const float*)d_in[1];
    const float* comp_g = (const float*)d_in[2];
    const float* comp_b = (const float*)d_in[3];
    const float* enc_w  = (const float*)d_in[4];
    const float* enc_g  = (const float*)d_in[5];
    const float* enc_b  = (const float*)d_in[6];
    float* out = (float*)d_out;

    cudaFuncSetAttribute(k_conv3mma, cudaFuncAttributeMaxDynamicSharedMemorySize, C3_SMEM);
    cudaFuncSetAttribute(k_reasm, cudaFuncAttributeMaxDynamicSharedMemorySize, REASM_SMEM);

    k_prep<<<320, 256>>>(comp_w, enc_w);                 // 0
    k_conv1<<<dim3(16, B), 256>>>(x);                    // 1
    k_act<<<dim3(32, B), 256>>>(comp_g, comp_b);         // 2
    k_conv3mma<<<dim3(32, B), 256, C3_SMEM>>>();         // 3  <- ncu slot
    k_fin2<<<OC2, 256>>>(enc_g, enc_b);                  // 4
    k_reasm<<<dim3(64, B), 256, REASM_SMEM>>>(x, out);   // 5
}

// round 14
// speedup vs baseline: 1.3934x; 1.3934x over previous
#include <cuda_runtime.h>
#include <cuda_bf16.h>
#include <cstdint>
#include <math.h>

// ---------------------------------------------------------------------------
// CARAFE fp32.  Round 14: conv3mma reverted to R12 (cp.async regression);
// k_act keeps grid(32,8); reasm tap loop fully unrolled for ILP.
// ---------------------------------------------------------------------------

#define B 8
#define CIN 128
#define MID 64
#define OC2 100
#define HW 4096
#define EPS 1e-5f

typedef unsigned long long u64;
typedef unsigned short u16;

__device__ __forceinline__ u64 pk(float lo, float hi) {
    u64 r; asm("mov.b64 %0,{%1,%2};" : "=l"(r) : "f"(lo), "f"(hi)); return r;
}
__device__ __forceinline__ void fma2(u64& d, u64 a, u64 b) {
    asm("fma.rn.f32x2 %0,%1,%2,%0;" : "+l"(d) : "l"(a), "l"(b));
}
__device__ __forceinline__ u64 add2(u64 a, u64 b) {
    u64 r; asm("add.rn.f32x2 %0,%1,%2;" : "=l"(r) : "l"(a), "l"(b)); return r;
}
__device__ __forceinline__ void unpk(u64 a, float& lo, float& hi) {
    asm("mov.b64 {%0,%1},%2;" : "=f"(lo), "=f"(hi) : "l"(a));
}
__device__ __forceinline__ u16 bfbits(float v) {
    __nv_bfloat16 h = __float2bfloat16(v);
    return *reinterpret_cast<u16*>(&h);
}
__device__ __forceinline__ float bf2f(u16 s) {
    __nv_bfloat16 h = *reinterpret_cast<__nv_bfloat16*>(&s);
    return __bfloat162float(h);
}
__device__ __forceinline__ uint32_t smem_u32(const void* p) {
    uint32_t a;
    asm("{ .reg .u64 t; cvta.to.shared.u64 t, %1; cvt.u32.u64 %0, t; }"
        : "=r"(a) : "l"(p));
    return a;
}

// mma.sync m16n8k16 row.col f32.bf16.bf16.f32
__device__ __forceinline__ void mmabf(float& d0, float& d1, float& d2, float& d3,
                                      uint32_t a0, uint32_t a1, uint32_t a2, uint32_t a3,
                                      uint32_t b0, uint32_t b1) {
    asm volatile(
        "mma.sync.aligned.m16n8k16.row.col.f32.bf16.bf16.f32 "
        "{%0,%1,%2,%3},{%4,%5,%6,%7},{%8,%9},{%0,%1,%2,%3};"
        : "+f"(d0), "+f"(d1), "+f"(d2), "+f"(d3)
        : "r"(a0), "r"(a1), "r"(a2), "r"(a3), "r"(b0), "r"(b1));
}
__device__ __forceinline__ void lm4(uint32_t& r0, uint32_t& r1, uint32_t& r2,
                                    uint32_t& r3, uint32_t a) {
    asm volatile("ldmatrix.sync.aligned.m8n8.x4.shared.b16 {%0,%1,%2,%3},[%4];"
                 : "=r"(r0), "=r"(r1), "=r"(r2), "=r"(r3) : "r"(a));
}
__device__ __forceinline__ void lm2(uint32_t& r0, uint32_t& r1, uint32_t a) {
    asm volatile("ldmatrix.sync.aligned.m8n8.x2.shared.b16 {%0,%1},[%2];"
                 : "=r"(r0), "=r"(r1) : "r"(a));
}

// scratch
__device__ __align__(16) float g_t1[B * MID * HW];
__device__ __align__(16) float g_t2[B * OC2 * HW];
__device__ float g_sc2[OC2], g_sh2[OC2];
__device__ __align__(16) float g_p1s[128 * 64], g_p1q[128 * 64];
__device__ __align__(16) float g_p2s[256 * 100], g_p2q[256 * 100];
__device__ __align__(16) float g_w1T[128 * 64];                 // [cc][oc]
__device__ __align__(16) u16 g_aH[B * HW * 64], g_aL[B * HW * 64];  // [b][px][c]
__device__ __align__(16) u16 g_wH[18 * 4096], g_wL[18 * 4096];  // [chunk][oc 128][k 32]

__device__ __forceinline__ void wred2(u64& s, u64& q) {
#pragma unroll
    for (int o = 16; o; o >>= 1) {
        s = add2(s, __shfl_down_sync(0xFFFFFFFFu, s, o));
        q = add2(q, __shfl_down_sync(0xFFFFFFFFu, q, o));
    }
}

// ---------------------------------------------------------------------------
// prep
// ---------------------------------------------------------------------------
__global__ void k_prep(const float* __restrict__ cw, const float* __restrict__ ew) {
    int idx = blockIdx.x * 256 + threadIdx.x;
    if (idx < 18 * 4096) {
        int chunk = idx >> 12;
        int r = idx & 4095;
        int oc = r >> 5, k = r & 31;
        int tap = chunk >> 1, half = chunk & 1;
        float v = 0.f;
        if (oc < 100) v = ew[(oc * 64 + half * 32 + k) * 9 + tap];
        u16 hb = bfbits(v);
        float hf = bf2f(hb);
        g_wH[idx] = hb;
        g_wL[idx] = bfbits(v - hf);
    } else if (idx < 18 * 4096 + 8192) {
        int j = idx - 18 * 4096;
        int cc = j >> 6, oc = j & 63;
        g_w1T[j] = cw[oc * 128 + cc];
    }
}

// ---------------------------------------------------------------------------
// conv1x1: grid(16,8) x 256.  thread: 4 px x 8 oc-pairs. + BN partials.
// ---------------------------------------------------------------------------
__global__ void k_conv1(const float* __restrict__ x) {
    __shared__ float xs[32][256];
    __shared__ __align__(16) float ws1[32][64];
    __shared__ u64 r_s[8][8], r_q[8][8];
    const int b = blockIdx.y;
    const int p0 = blockIdx.x * 256;
    const int tid = threadIdx.x;
    const int pixg = tid & 63;
    const int ocg = tid >> 6;

    u64 acc[8][4];
#pragma unroll
    for (int p = 0; p < 8; p++)
#pragma unroll
        for (int j = 0; j < 4; j++) acc[p][j] = 0ull;

    for (int c0 = 0; c0 < CIN; c0 += 32) {
        __syncthreads();
#pragma unroll 4
        for (int j = 0; j < 32; j++)
            xs[j][tid] = x[((size_t)(b * CIN + c0 + j) << 12) + p0 + tid];
#pragma unroll
        for (int j = 0; j < 8; j++) {
            int idx = j * 256 + tid;
            int oc = idx & 63, cc = idx >> 6;
            ws1[cc][oc] = g_w1T[(c0 + cc) * 64 + oc];
        }
        __syncthreads();
#pragma unroll 4
        for (int cc = 0; cc < 32; cc++) {
            float4 xv = *(const float4*)&xs[cc][pixg * 4];
            u64 P0 = pk(xv.x, xv.x), P1 = pk(xv.y, xv.y);
            u64 P2 = pk(xv.z, xv.z), P3 = pk(xv.w, xv.w);
            const u64* wp = (const u64*)&ws1[cc][ocg * 16];
#pragma unroll
            for (int p = 0; p < 8; p++) {
                u64 w = wp[p];
                fma2(acc[p][0], w, P0);
                fma2(acc[p][1], w, P1);
                fma2(acc[p][2], w, P2);
                fma2(acc[p][3], w, P3);
            }
        }
    }
    const int lane = tid & 31, wid = tid >> 5;
#pragma unroll
    for (int p = 0; p < 8; p++) {
        int oce = ocg * 16 + 2 * p;
        float e0, o0, e1, o1, e2, o2, e3, o3;
        unpk(acc[p][0], e0, o0); unpk(acc[p][1], e1, o1);
        unpk(acc[p][2], e2, o2); unpk(acc[p][3], e3, o3);
        *(float4*)&g_t1[((size_t)(b * MID + oce) << 12) + p0 + pixg * 4] =
            make_float4(e0, e1, e2, e3);
        *(float4*)&g_t1[((size_t)(b * MID + oce + 1) << 12) + p0 + pixg * 4] =
            make_float4(o0, o1, o2, o3);
        u64 s = add2(add2(acc[p][0], acc[p][1]), add2(acc[p][2], acc[p][3]));
        u64 q = 0ull;
        fma2(q, acc[p][0], acc[p][0]); fma2(q, acc[p][1], acc[p][1]);
        fma2(q, acc[p][2], acc[p][2]); fma2(q, acc[p][3], acc[p][3]);
        wred2(s, q);
        if (lane == 0) { r_s[wid][p] = s; r_q[wid][p] = q; }
    }
    __syncthreads();
    if (tid < 32) {
        int g = tid >> 3, p = tid & 7;
        u64 s = add2(r_s[2 * g][p], r_s[2 * g + 1][p]);
        u64 q = add2(r_q[2 * g][p], r_q[2 * g + 1][p]);
        int blk = b * 16 + blockIdx.x;
        *(u64*)&g_p1s[blk * 64 + 2 * (g * 8 + p)] = s;
        *(u64*)&g_p1q[blk * 64 + 2 * (g * 8 + p)] = q;
    }
}

// ---------------------------------------------------------------------------
// act (fin1 fused): grid(32,8) x 256; block = 2 rows.
// ---------------------------------------------------------------------------
__global__ void k_act(const float* __restrict__ gam, const float* __restrict__ bet) {
    __shared__ float ts[64][65];
    __shared__ float ps[4][64], pq[4][64];
    __shared__ float sc[64], sh[64];
    const int y0 = blockIdx.x * 2, b = blockIdx.y;
    const int tid = threadIdx.x;

    {
        int c = tid & 63, gp = tid >> 6;
        float s = 0.f, q = 0.f;
#pragma unroll 8
        for (int i = 0; i < 32; i++) {
            int blk = gp * 32 + i;
            s += g_p1s[blk * 64 + c];
            q += g_p1q[blk * 64 + c];
        }
        ps[gp][c] = s; pq[gp][c] = q;
    }
    __syncthreads();
    if (tid < 64) {
        float s = ps[0][tid] + ps[1][tid] + ps[2][tid] + ps[3][tid];
        float q = pq[0][tid] + pq[1][tid] + pq[2][tid] + pq[3][tid];
        const float inv = 1.f / 32768.f;
        float m = s * inv, var = fmaf(-m, m, q * inv);
        float k = gam[tid] * rsqrtf(var + EPS);
        sc[tid] = k; sh[tid] = bet[tid] - m * k;
    }

#pragma unroll 1
    for (int ry = 0; ry < 2; ry++) {
        const int y = y0 + ry;
        __syncthreads();
#pragma unroll
        for (int it = 0; it < 4; it++) {
            int idx = it * 256 + tid;
            int c = idx >> 4, x4 = idx & 15;
            float4 v = *(const float4*)&g_t1[((size_t)(b * MID + c) << 12)
                                             + (y << 6) + x4 * 4];
            float z0 = fmaf(v.x, sc[c], sh[c]);
            float z1 = fmaf(v.y, sc[c], sh[c]);
            float z2 = fmaf(v.z, sc[c], sh[c]);
            float z3 = fmaf(v.w, sc[c], sh[c]);
            ts[c][x4 * 4 + 0] = z0 * (1.f / (1.f + __expf(-z0)));
            ts[c][x4 * 4 + 1] = z1 * (1.f / (1.f + __expf(-z1)));
            ts[c][x4 * 4 + 2] = z2 * (1.f / (1.f + __expf(-z2)));
            ts[c][x4 * 4 + 3] = z3 * (1.f / (1.f + __expf(-z3)));
        }
        __syncthreads();
        const size_t rowbase = (size_t)((b << 6) + y) << 12;
        uint32_t* dH = (uint32_t*)(g_aH + rowbase);
        uint32_t* dL = (uint32_t*)(g_aL + rowbase);
#pragma unroll
        for (int it = 0; it < 8; it++) {
            int idx = it * 256 + tid;
            int xx = idx >> 5, cp = idx & 31;
            float v0 = ts[2 * cp][xx], v1 = ts[2 * cp + 1][xx];
            u16 h0 = bfbits(v0), h1 = bfbits(v1);
            u16 l0 = bfbits(v0 - bf2f(h0)), l1 = bfbits(v1 - bf2f(h1));
            dH[xx * 32 + cp] = (uint32_t)h0 | ((uint32_t)h1 << 16);
            dL[xx * 32 + cp] = (uint32_t)l0 | ((uint32_t)l1 << 16);
        }
    }
}

// ---------------------------------------------------------------------------
// conv3 via mma.sync bf16x3 + ldmatrix (R12 version).  grid(32,8) x 256.
// ---------------------------------------------------------------------------
#define C3_SMEM 40960

__global__ __launch_bounds__(256) void k_conv3mma() {
    extern __shared__ __align__(16) char smc[];
    __shared__ float sAcc[128], qAcc[128];
    const uint32_t sb = smem_u32(smc);
    const int tid = threadIdx.x;
    const int tile = blockIdx.x, b = blockIdx.y;
    const int p0 = tile * 128;
    const int lane = tid & 31, wid = tid >> 5;
    const int g = lane >> 2, tg = lane & 3;
    const int wm = wid >> 1, wn = wid & 1;
    const int m0 = wm * 32, n0 = wn * 64;

    if (tid < 128) { sAcc[tid] = 0.f; qAcc[tid] = 0.f; }

    float acc[2][8][4];
#pragma unroll
    for (int mt = 0; mt < 2; mt++)
#pragma unroll
        for (int nt = 0; nt < 8; nt++)
#pragma unroll
            for (int j = 0; j < 4; j++) acc[mt][nt][j] = 0.f;

    const uint32_t aAddr = sb + (uint32_t)(m0 + (lane & 15)) * 80 + (lane >> 4) * 16;
    const uint32_t bAddr = sb + 20480u + (uint32_t)(n0 + (lane & 7)) * 80 +
                           ((lane >> 3) & 3) * 16;

#pragma unroll 1
    for (int chunk = 0; chunk < 18; chunk++) {
        const int tap = chunk >> 1, half = chunk & 1;
        const int dy = tap / 3 - 1, dx = tap - (tap / 3) * 3 - 1;
        __syncthreads();
#pragma unroll
        for (int it = 0; it < 8; it++) {
            int idx = it * 256 + tid;
            if (idx < 1024) {
                int arr = idx >> 9, j = idx & 511;
                int pxl = j >> 2, u = j & 3;
                int gy = tile * 2 + (pxl >> 6) + dy;
                int gx = (pxl & 63) + dx;
                float4 v = make_float4(0.f, 0.f, 0.f, 0.f);
                if ((unsigned)gy < 64u && (unsigned)gx < 64u) {
                    const u16* src = (arr ? g_aL : g_aH) +
                        ((size_t)(b << 12) + (gy << 6) + gx) * 64 + half * 32 + u * 8;
                    v = *(const float4*)src;
                }
                *(float4*)(smc + arr * 10240 + pxl * 80 + u * 16) = v;
            } else {
                int j = idx - 1024;
                int arr = j >> 9, jb = j & 511;
                int oc = jb >> 2, u = jb & 3;
                const u16* src = (arr ? g_wL : g_wH) + (chunk << 12) + oc * 32 + u * 8;
                *(float4*)(smc + 20480 + arr * 10240 + oc * 80 + u * 16) =
                    *(const float4*)src;
            }
        }
        __syncthreads();

#pragma unroll
        for (int ks = 0; ks < 2; ks++) {
            const uint32_t ko = ks * 32;
            uint32_t aH[2][4], aL[2][4];
#pragma unroll
            for (int mt = 0; mt < 2; mt++) {
                uint32_t a = aAddr + mt * (16 * 80) + ko;
                lm4(aH[mt][0], aH[mt][1], aH[mt][2], aH[mt][3], a);
                lm4(aL[mt][0], aL[mt][1], aL[mt][2], aL[mt][3], a + 10240);
            }
#pragma unroll
            for (int nt = 0; nt < 8; nt++) {
                uint32_t ba = bAddr + nt * (8 * 80) + ko;
                uint32_t bH0, bH1, bL0, bL1;
                lm2(bH0, bH1, ba);
                lm2(bL0, bL1, ba + 10240);
#pragma unroll
                for (int mt = 0; mt < 2; mt++) {
                    float* d = acc[mt][nt];
                    mmabf(d[0], d[1], d[2], d[3],
                          aH[mt][0], aH[mt][1], aH[mt][2], aH[mt][3], bH0, bH1);
                    mmabf(d[0], d[1], d[2], d[3],
                          aH[mt][0], aH[mt][1], aH[mt][2], aH[mt][3], bL0, bL1);
                    mmabf(d[0], d[1], d[2], d[3],
                          aL[mt][0], aL[mt][1], aL[mt][2], aL[mt][3], bH0, bH1);
                }
            }
        }
    }

    // epilogue: store + BN2 partials
#pragma unroll
    for (int mt = 0; mt < 2; mt++) {
#pragma unroll
        for (int nt = 0; nt < 8; nt++) {
            int oc0 = n0 + nt * 8 + 2 * tg;
            int pxl = m0 + mt * 16 + g;
            float c0 = acc[mt][nt][0], c1 = acc[mt][nt][1];
            float c2 = acc[mt][nt][2], c3 = acc[mt][nt][3];
            if (oc0 < 100) {
                size_t ob = ((size_t)(b * OC2 + oc0) << 12) + p0 + pxl;
                g_t2[ob] = c0;
                g_t2[ob + 8] = c2;
                if (oc0 + 1 < 100) {
                    g_t2[ob + HW] = c1;
                    g_t2[ob + HW + 8] = c3;
                }
            }
            float s0 = c0 + c2, q0 = fmaf(c0, c0, c2 * c2);
            float s1 = c1 + c3, q1 = fmaf(c1, c1, c3 * c3);
#pragma unroll
            for (int o = 16; o >= 4; o >>= 1) {
                s0 += __shfl_down_sync(0xFFFFFFFFu, s0, o);
                q0 += __shfl_down_sync(0xFFFFFFFFu, q0, o);
                s1 += __shfl_down_sync(0xFFFFFFFFu, s1, o);
                q1 += __shfl_down_sync(0xFFFFFFFFu, q1, o);
            }
            if (lane < 4 && oc0 < 100) {
                atomicAdd(&sAcc[oc0], s0);
                atomicAdd(&qAcc[oc0], q0);
                if (oc0 + 1 < 100) {
                    atomicAdd(&sAcc[oc0 + 1], s1);
                    atomicAdd(&qAcc[oc0 + 1], q1);
                }
            }
        }
    }
    __syncthreads();
    if (tid < 100) {
        int blk = b * 32 + tile;
        g_p2s[blk * 100 + tid] = sAcc[tid];
        g_p2q[blk * 100 + tid] = qAcc[tid];
    }
}

__global__ void k_fin2(const float* __restrict__ gam, const float* __restrict__ bet) {
    const int oc = blockIdx.x, t = threadIdx.x;
    float s = g_p2s[t * 100 + oc], q = g_p2q[t * 100 + oc];
#pragma unroll
    for (int o = 16; o; o >>= 1) {
        s += __shfl_down_sync(0xFFFFFFFFu, s, o);
        q += __shfl_down_sync(0xFFFFFFFFu, q, o);
    }
    __shared__ float ss[8], qq[8];
    if ((t & 31) == 0) { ss[t >> 5] = s; qq[t >> 5] = q; }
    __syncthreads();
    if (t == 0) {
        s = 0.f; q = 0.f;
#pragma unroll
        for (int i = 0; i < 8; i++) { s += ss[i]; q += qq[i]; }
        const float inv = 1.f / 32768.f;
        float m = s * inv, var = fmaf(-m, m, q * inv);
        float k = gam[oc] * rsqrtf(var + EPS);
        g_sc2[oc] = k; g_sh2[oc] = bet[oc] - m * k;
    }
}

// ---------------------------------------------------------------------------
// reassembly: 25-tap loop fully unrolled (straight-line, deep ILP window).
// ---------------------------------------------------------------------------
#define RPOS 140
#define REASM_SMEM ((144 * RPOS + 256 * 25) * 4)

__global__ __launch_bounds__(256, 2) void k_reasm(const float* __restrict__ x,
                                                  float* __restrict__ out) {
    extern __shared__ float sm[];
    float* srcs = sm;
    float* wgt = sm + 144 * RPOS;

    const int b = blockIdx.y;
    const int ti0 = (blockIdx.x >> 3) << 4;
    const int tj0 = (blockIdx.x & 7) << 4;
    const int tid = threadIdx.x;
    const int sy0 = (ti0 >> 1) - 2;
    const int sx0 = (tj0 >> 1) - 2;

#pragma unroll 4
    for (int it = 0; it < 72; it++) {
        int idx = tid + it * 256;
        int c = idx / 144;
        int pos = idx - c * 144;
        int yy = pos / 12;
        int xx = pos - yy * 12;
        int gy = sy0 + yy, gx = sx0 + xx;
        float v = 0.f;
        if ((unsigned)gy < 64u && (unsigned)gx < 64u)
            v = x[((size_t)(b * CIN + c) << 12) + (gy << 6) + gx];
        int p = c >> 1;
        srcs[pos * RPOS + (p >> 4) * 36 + (p & 15) * 2 + (c & 1)] = v;
    }

    {
        int py = tid >> 4, px = tid & 15;
        int gi = ti0 + py, gj = tj0 + px;
        int y0 = gi >> 1, x0 = gj >> 1;
        int sub = ((gi & 1) << 1) | (gj & 1);
        float l[25];
        float mx = -1e30f;
#pragma unroll
        for (int k = 0; k < 25; k++) {
            int ch = (k << 2) + sub;
            float v = fmaf(g_t2[((size_t)(b * OC2 + ch) << 12) + (y0 << 6) + x0],
                           g_sc2[ch], g_sh2[ch]);
            l[k] = v;
            mx = fmaxf(mx, v);
        }
        float s = 0.f;
#pragma unroll
        for (int k = 0; k < 25; k++) { l[k] = __expf(l[k] - mx); s += l[k]; }
        float inv = 1.f / s;
#pragma unroll
        for (int k = 0; k < 25; k++) wgt[tid * 25 + k] = l[k] * inv;
    }
    __syncthreads();

    const int s4 = tid & 3;
    const int quad = tid >> 2;
    const int qy = quad >> 3, qx = quad & 7;
    const int posb = qy * 12 + qx;
    const float* wp0 = &wgt[(2 * qy * 16 + 2 * qx) * 25];
    const int gi0 = ti0 + 2 * qy;
    const int gj = tj0 + 2 * qx;

#pragma unroll 1
    for (int g = 0; g < 2; g++) {
        u64 a[2][2][8];
#pragma unroll
        for (int di = 0; di < 2; di++)
#pragma unroll
            for (int dj = 0; dj < 2; dj++)
#pragma unroll
                for (int j = 0; j < 8; j++) a[di][dj][j] = 0ull;

        // FULLY UNROLLED 25 taps: straight-line, loads pipelined by ptxas
#pragma unroll
        for (int t = 0; t < 25; t++) {
            int dy = t / 5, dx = t - 5 * (t / 5);
            float w00 = wp0[t], w01 = wp0[25 + t];
            float w10 = wp0[400 + t], w11 = wp0[425 + t];
            u64 W00 = pk(w00, w00), W01 = pk(w01, w01);
            u64 W10 = pk(w10, w10), W11 = pk(w11, w11);
            const ulonglong2* r = (const ulonglong2*)(
                srcs + (posb + dy * 12 + dx) * RPOS + s4 * 36 + g * 16);
            ulonglong2 q0 = r[0], q1 = r[1], q2 = r[2], q3 = r[3];
            u64 sv[8] = {q0.x, q0.y, q1.x, q1.y, q2.x, q2.y, q3.x, q3.y};
#pragma unroll
            for (int j = 0; j < 8; j++) {
                fma2(a[0][0][j], W00, sv[j]);
                fma2(a[0][1][j], W01, sv[j]);
                fma2(a[1][0][j], W10, sv[j]);
                fma2(a[1][1][j], W11, sv[j]);
            }
        }

#pragma unroll
        for (int j = 0; j < 8; j++) {
            int p = s4 * 16 + g * 8 + j;
            int c = 2 * p;
#pragma unroll
            for (int di = 0; di < 2; di++) {
                float e0, h0, e1, h1;
                unpk(a[di][0][j], e0, h0);
                unpk(a[di][1][j], e1, h1);
                size_t ob = (((size_t)(b * CIN + c) << 7) + gi0 + di) * 128 + gj;
                *(float2*)&out[ob] = make_float2(e0, e1);
                *(float2*)&out[ob + 16384] = make_float2(h0, h1);
            }
        }
    }
}

// ---------------------------------------------------------------------------
extern "C" void kernel_launch(void* const* d_in, const int* in_sizes, int n_in,
                              void* d_out, int out_size) {
    const float* x      = (const float*)d_in[0];
    const float* comp_w = (const float*)d_in[1];
    const float* comp_g = (const float*)d_in[2];
    const float* comp_b = (const float*)d_in[3];
    const float* enc_w  = (const float*)d_in[4];
    const float* enc_g  = (const float*)d_in[5];
    const float* enc_b  = (const float*)d_in[6];
    float* out = (float*)d_out;

    cudaFuncSetAttribute(k_conv3mma, cudaFuncAttributeMaxDynamicSharedMemorySize, C3_SMEM);
    cudaFuncSetAttribute(k_reasm, cudaFuncAttributeMaxDynamicSharedMemorySize, REASM_SMEM);

    k_prep<<<320, 256>>>(comp_w, enc_w);                 // 0
    k_conv1<<<dim3(16, B), 256>>>(x);                    // 1
    k_act<<<dim3(32, B), 256>>>(comp_g, comp_b);         // 2
    k_conv3mma<<<dim3(32, B), 256, C3_SMEM>>>();         // 3  <- ncu slot
    k_fin2<<<OC2, 256>>>(enc_g, enc_b);                  // 4
    k_reasm<<<dim3(64, B), 256, REASM_SMEM>>>(x, out);   // 5
}

// round 15
// speedup vs baseline: 1.4291x; 1.0256x over previous
#include <cuda_runtime.h>
#include <cuda_bf16.h>
#include <cstdint>
#include <math.h>

// ---------------------------------------------------------------------------
// CARAFE fp32.  Round 15: conv3mma A-window resident (staged once per half,
// taps addressed via warp-uniform ldmatrix offsets), B reg-pipelined double
// buffer; reasm reverted to R12 grouped loop (full-unroll spill regression).
// ---------------------------------------------------------------------------

#define B 8
#define CIN 128
#define MID 64
#define OC2 100
#define HW 4096
#define EPS 1e-5f

typedef unsigned long long u64;
typedef unsigned short u16;

__device__ __forceinline__ u64 pk(float lo, float hi) {
    u64 r; asm("mov.b64 %0,{%1,%2};" : "=l"(r) : "f"(lo), "f"(hi)); return r;
}
__device__ __forceinline__ void fma2(u64& d, u64 a, u64 b) {
    asm("fma.rn.f32x2 %0,%1,%2,%0;" : "+l"(d) : "l"(a), "l"(b));
}
__device__ __forceinline__ u64 add2(u64 a, u64 b) {
    u64 r; asm("add.rn.f32x2 %0,%1,%2;" : "=l"(r) : "l"(a), "l"(b)); return r;
}
__device__ __forceinline__ void unpk(u64 a, float& lo, float& hi) {
    asm("mov.b64 {%0,%1},%2;" : "=f"(lo), "=f"(hi) : "l"(a));
}
__device__ __forceinline__ u16 bfbits(float v) {
    __nv_bfloat16 h = __float2bfloat16(v);
    return *reinterpret_cast<u16*>(&h);
}
__device__ __forceinline__ float bf2f(u16 s) {
    __nv_bfloat16 h = *reinterpret_cast<__nv_bfloat16*>(&s);
    return __bfloat162float(h);
}
__device__ __forceinline__ uint32_t smem_u32(const void* p) {
    uint32_t a;
    asm("{ .reg .u64 t; cvta.to.shared.u64 t, %1; cvt.u32.u64 %0, t; }"
        : "=r"(a) : "l"(p));
    return a;
}

__device__ __forceinline__ void mmabf(float& d0, float& d1, float& d2, float& d3,
                                      uint32_t a0, uint32_t a1, uint32_t a2, uint32_t a3,
                                      uint32_t b0, uint32_t b1) {
    asm volatile(
        "mma.sync.aligned.m16n8k16.row.col.f32.bf16.bf16.f32 "
        "{%0,%1,%2,%3},{%4,%5,%6,%7},{%8,%9},{%0,%1,%2,%3};"
        : "+f"(d0), "+f"(d1), "+f"(d2), "+f"(d3)
        : "r"(a0), "r"(a1), "r"(a2), "r"(a3), "r"(b0), "r"(b1));
}
__device__ __forceinline__ void lm4(uint32_t& r0, uint32_t& r1, uint32_t& r2,
                                    uint32_t& r3, uint32_t a) {
    asm volatile("ldmatrix.sync.aligned.m8n8.x4.shared.b16 {%0,%1,%2,%3},[%4];"
                 : "=r"(r0), "=r"(r1), "=r"(r2), "=r"(r3) : "r"(a));
}
__device__ __forceinline__ void lm2(uint32_t& r0, uint32_t& r1, uint32_t a) {
    asm volatile("ldmatrix.sync.aligned.m8n8.x2.shared.b16 {%0,%1},[%2];"
                 : "=r"(r0), "=r"(r1) : "r"(a));
}

// scratch
__device__ __align__(16) float g_t1[B * MID * HW];
__device__ __align__(16) float g_t2[B * OC2 * HW];
__device__ float g_sc2[OC2], g_sh2[OC2];
__device__ __align__(16) float g_p1s[128 * 64], g_p1q[128 * 64];
__device__ __align__(16) float g_p2s[256 * 100], g_p2q[256 * 100];
__device__ __align__(16) float g_w1T[128 * 64];                 // [cc][oc]
__device__ __align__(16) u16 g_aH[B * HW * 64], g_aL[B * HW * 64];  // [b][px][c]
__device__ __align__(16) u16 g_wH[18 * 4096], g_wL[18 * 4096];  // [chunk][oc 128][k 32]

__device__ __forceinline__ void wred2(u64& s, u64& q) {
#pragma unroll
    for (int o = 16; o; o >>= 1) {
        s = add2(s, __shfl_down_sync(0xFFFFFFFFu, s, o));
        q = add2(q, __shfl_down_sync(0xFFFFFFFFu, q, o));
    }
}

// ---------------------------------------------------------------------------
// prep
// ---------------------------------------------------------------------------
__global__ void k_prep(const float* __restrict__ cw, const float* __restrict__ ew) {
    int idx = blockIdx.x * 256 + threadIdx.x;
    if (idx < 18 * 4096) {
        int chunk = idx >> 12;
        int r = idx & 4095;
        int oc = r >> 5, k = r & 31;
        int tap = chunk >> 1, half = chunk & 1;
        float v = 0.f;
        if (oc < 100) v = ew[(oc * 64 + half * 32 + k) * 9 + tap];
        u16 hb = bfbits(v);
        float hf = bf2f(hb);
        g_wH[idx] = hb;
        g_wL[idx] = bfbits(v - hf);
    } else if (idx < 18 * 4096 + 8192) {
        int j = idx - 18 * 4096;
        int cc = j >> 6, oc = j & 63;
        g_w1T[j] = cw[oc * 128 + cc];
    }
}

// ---------------------------------------------------------------------------
// conv1x1 (unchanged): grid(16,8) x 256.
// ---------------------------------------------------------------------------
__global__ void k_conv1(const float* __restrict__ x) {
    __shared__ float xs[32][256];
    __shared__ __align__(16) float ws1[32][64];
    __shared__ u64 r_s[8][8], r_q[8][8];
    const int b = blockIdx.y;
    const int p0 = blockIdx.x * 256;
    const int tid = threadIdx.x;
    const int pixg = tid & 63;
    const int ocg = tid >> 6;

    u64 acc[8][4];
#pragma unroll
    for (int p = 0; p < 8; p++)
#pragma unroll
        for (int j = 0; j < 4; j++) acc[p][j] = 0ull;

    for (int c0 = 0; c0 < CIN; c0 += 32) {
        __syncthreads();
#pragma unroll 4
        for (int j = 0; j < 32; j++)
            xs[j][tid] = x[((size_t)(b * CIN + c0 + j) << 12) + p0 + tid];
#pragma unroll
        for (int j = 0; j < 8; j++) {
            int idx = j * 256 + tid;
            int oc = idx & 63, cc = idx >> 6;
            ws1[cc][oc] = g_w1T[(c0 + cc) * 64 + oc];
        }
        __syncthreads();
#pragma unroll 4
        for (int cc = 0; cc < 32; cc++) {
            float4 xv = *(const float4*)&xs[cc][pixg * 4];
            u64 P0 = pk(xv.x, xv.x), P1 = pk(xv.y, xv.y);
            u64 P2 = pk(xv.z, xv.z), P3 = pk(xv.w, xv.w);
            const u64* wp = (const u64*)&ws1[cc][ocg * 16];
#pragma unroll
            for (int p = 0; p < 8; p++) {
                u64 w = wp[p];
                fma2(acc[p][0], w, P0);
                fma2(acc[p][1], w, P1);
                fma2(acc[p][2], w, P2);
                fma2(acc[p][3], w, P3);
            }
        }
    }
    const int lane = tid & 31, wid = tid >> 5;
#pragma unroll
    for (int p = 0; p < 8; p++) {
        int oce = ocg * 16 + 2 * p;
        float e0, o0, e1, o1, e2, o2, e3, o3;
        unpk(acc[p][0], e0, o0); unpk(acc[p][1], e1, o1);
        unpk(acc[p][2], e2, o2); unpk(acc[p][3], e3, o3);
        *(float4*)&g_t1[((size_t)(b * MID + oce) << 12) + p0 + pixg * 4] =
            make_float4(e0, e1, e2, e3);
        *(float4*)&g_t1[((size_t)(b * MID + oce + 1) << 12) + p0 + pixg * 4] =
            make_float4(o0, o1, o2, o3);
        u64 s = add2(add2(acc[p][0], acc[p][1]), add2(acc[p][2], acc[p][3]));
        u64 q = 0ull;
        fma2(q, acc[p][0], acc[p][0]); fma2(q, acc[p][1], acc[p][1]);
        fma2(q, acc[p][2], acc[p][2]); fma2(q, acc[p][3], acc[p][3]);
        wred2(s, q);
        if (lane == 0) { r_s[wid][p] = s; r_q[wid][p] = q; }
    }
    __syncthreads();
    if (tid < 32) {
        int g = tid >> 3, p = tid & 7;
        u64 s = add2(r_s[2 * g][p], r_s[2 * g + 1][p]);
        u64 q = add2(r_q[2 * g][p], r_q[2 * g + 1][p]);
        int blk = b * 16 + blockIdx.x;
        *(u64*)&g_p1s[blk * 64 + 2 * (g * 8 + p)] = s;
        *(u64*)&g_p1q[blk * 64 + 2 * (g * 8 + p)] = q;
    }
}

// ---------------------------------------------------------------------------
// act (fin1 fused): grid(32,8) x 256; block = 2 rows.
// ---------------------------------------------------------------------------
__global__ void k_act(const float* __restrict__ gam, const float* __restrict__ bet) {
    __shared__ float ts[64][65];
    __shared__ float ps[4][64], pq[4][64];
    __shared__ float sc[64], sh[64];
    const int y0 = blockIdx.x * 2, b = blockIdx.y;
    const int tid = threadIdx.x;

    {
        int c = tid & 63, gp = tid >> 6;
        float s = 0.f, q = 0.f;
#pragma unroll 8
        for (int i = 0; i < 32; i++) {
            int blk = gp * 32 + i;
            s += g_p1s[blk * 64 + c];
            q += g_p1q[blk * 64 + c];
        }
        ps[gp][c] = s; pq[gp][c] = q;
    }
    __syncthreads();
    if (tid < 64) {
        float s = ps[0][tid] + ps[1][tid] + ps[2][tid] + ps[3][tid];
        float q = pq[0][tid] + pq[1][tid] + pq[2][tid] + pq[3][tid];
        const float inv = 1.f / 32768.f;
        float m = s * inv, var = fmaf(-m, m, q * inv);
        float k = gam[tid] * rsqrtf(var + EPS);
        sc[tid] = k; sh[tid] = bet[tid] - m * k;
    }

#pragma unroll 1
    for (int ry = 0; ry < 2; ry++) {
        const int y = y0 + ry;
        __syncthreads();
#pragma unroll
        for (int it = 0; it < 4; it++) {
            int idx = it * 256 + tid;
            int c = idx >> 4, x4 = idx & 15;
            float4 v = *(const float4*)&g_t1[((size_t)(b * MID + c) << 12)
                                             + (y << 6) + x4 * 4];
            float z0 = fmaf(v.x, sc[c], sh[c]);
            float z1 = fmaf(v.y, sc[c], sh[c]);
            float z2 = fmaf(v.z, sc[c], sh[c]);
            float z3 = fmaf(v.w, sc[c], sh[c]);
            ts[c][x4 * 4 + 0] = z0 * (1.f / (1.f + __expf(-z0)));
            ts[c][x4 * 4 + 1] = z1 * (1.f / (1.f + __expf(-z1)));
            ts[c][x4 * 4 + 2] = z2 * (1.f / (1.f + __expf(-z2)));
            ts[c][x4 * 4 + 3] = z3 * (1.f / (1.f + __expf(-z3)));
        }
        __syncthreads();
        const size_t rowbase = (size_t)((b << 6) + y) << 12;
        uint32_t* dH = (uint32_t*)(g_aH + rowbase);
        uint32_t* dL = (uint32_t*)(g_aL + rowbase);
#pragma unroll
        for (int it = 0; it < 8; it++) {
            int idx = it * 256 + tid;
            int xx = idx >> 5, cp = idx & 31;
            float v0 = ts[2 * cp][xx], v1 = ts[2 * cp + 1][xx];
            u16 h0 = bfbits(v0), h1 = bfbits(v1);
            u16 l0 = bfbits(v0 - bf2f(h0)), l1 = bfbits(v1 - bf2f(h1));
            dH[xx * 32 + cp] = (uint32_t)h0 | ((uint32_t)h1 << 16);
            dL[xx * 32 + cp] = (uint32_t)l0 | ((uint32_t)l1 << 16);
        }
    }
}

// ---------------------------------------------------------------------------
// conv3 v2: A window resident per half; B reg-pipelined double buffer.
// smem layout (bytes):
//   A: [arr 2][px 264 = r*66+cc][80]   @ 0 / 21120       (42240 total)
//   B: [buf 2][arr 2][oc 128][80]      @ 42240 (+buf*20480, +arr*10240)
// ---------------------------------------------------------------------------
#define ABYTES 42240
#define C3_SMEM (ABYTES + 40960 + 256)

__device__ __forceinline__ void ldB(float4* rb, int chunk, int tid) {
#pragma unroll
    for (int it = 0; it < 4; it++) {
        int j = it * 256 + tid;
        int arr = j >> 9, jb = j & 511;
        int oc = jb >> 2, u = jb & 3;
        const u16* src = (arr ? g_wL : g_wH) + (chunk << 12) + oc * 32 + u * 8;
        rb[it] = *(const float4*)src;
    }
}
__device__ __forceinline__ void stB(char* smc, uint32_t boff, const float4* rb, int tid) {
#pragma unroll
    for (int it = 0; it < 4; it++) {
        int j = it * 256 + tid;
        int arr = j >> 9, jb = j & 511;
        int oc = jb >> 2, u = jb & 3;
        *(float4*)(smc + boff + arr * 10240 + oc * 80 + u * 16) = rb[it];
    }
}

__global__ __launch_bounds__(256) void k_conv3mma() {
    extern __shared__ __align__(16) char smc[];
    __shared__ float sAcc[128], qAcc[128];
    const uint32_t sb = smem_u32(smc);
    const int tid = threadIdx.x;
    const int tile = blockIdx.x, b = blockIdx.y;
    const int p0 = tile * 128;
    const int lane = tid & 31, wid = tid >> 5;
    const int g = lane >> 2, tg = lane & 3;
    const int wm = wid >> 1, wn = wid & 1;
    const int m0 = wm * 32, n0 = wn * 64;

    if (tid < 128) { sAcc[tid] = 0.f; qAcc[tid] = 0.f; }

    float acc[2][8][4];
#pragma unroll
    for (int mt = 0; mt < 2; mt++)
#pragma unroll
        for (int nt = 0; nt < 8; nt++)
#pragma unroll
            for (int j = 0; j < 4; j++) acc[mt][nt][j] = 0.f;

    // per-lane ldmatrix address components
    uint32_t aoffm[2];
#pragma unroll
    for (int mt = 0; mt < 2; mt++) {
        int pxl = m0 + mt * 16 + (lane & 15);
        int ty = pxl >> 6, xx = pxl & 63;
        aoffm[mt] = (uint32_t)(((ty + 1) * 66 + xx + 1) * 80) + ((lane >> 4) << 4);
    }
    const uint32_t blane = (uint32_t)((n0 + (lane & 7)) * 80) + (((lane >> 3) & 3) << 4);

#pragma unroll 1
    for (int half = 0; half < 2; half++) {
        __syncthreads();   // prior compute done before A overwrite
        // stage A window [2 arr][4 rows][66 cols] for this half
        for (int idx = tid; idx < 2112; idx += 256) {
            int arr = idx / 1056;
            int j = idx - arr * 1056;
            int px = j >> 2, u = j & 3;
            int r = px / 66, cc = px - r * 66;
            int gy = tile * 2 - 1 + r, gx = cc - 1;
            float4 v = make_float4(0.f, 0.f, 0.f, 0.f);
            if ((unsigned)gy < 64u && (unsigned)gx < 64u) {
                const u16* src = (arr ? g_aL : g_aH) +
                    ((size_t)(b << 12) + (gy << 6) + gx) * 64 + half * 32 + u * 8;
                v = *(const float4*)src;
            }
            *(float4*)(smc + arr * 21120 + px * 80 + u * 16) = v;
        }
        float4 rb[4];
        ldB(rb, half, tid);                   // chunk = 0*2+half
        __syncthreads();                      // A visible
        stB(smc, ABYTES, rb, tid);            // buf 0
        __syncthreads();                      // B visible

#pragma unroll 1
        for (int tap = 0; tap < 9; tap++) {
            if (tap < 8) ldB(rb, (tap + 1) * 2 + half, tid);
            const int dyq = tap / 3;
            const int tapoff = ((dyq - 1) * 66 + (tap - 3 * dyq - 1)) * 80;
            const uint32_t bb = ABYTES + (uint32_t)((tap & 1) * 20480);

#pragma unroll
            for (int ks = 0; ks < 2; ks++) {
                const uint32_t ko = ks * 32;
                uint32_t aH[2][4], aL[2][4];
#pragma unroll
                for (int mt = 0; mt < 2; mt++) {
                    uint32_t a = sb + aoffm[mt] + tapoff + ko;
                    lm4(aH[mt][0], aH[mt][1], aH[mt][2], aH[mt][3], a);
                    lm4(aL[mt][0], aL[mt][1], aL[mt][2], aL[mt][3], a + 21120);
                }
#pragma unroll
                for (int nt = 0; nt < 8; nt++) {
                    uint32_t ba = sb + bb + blane + nt * 640 + ko;
                    uint32_t bH0, bH1, bL0, bL1;
                    lm2(bH0, bH1, ba);
                    lm2(bL0, bL1, ba + 10240);
#pragma unroll
                    for (int mt = 0; mt < 2; mt++) {
                        float* d = acc[mt][nt];
                        mmabf(d[0], d[1], d[2], d[3],
                              aH[mt][0], aH[mt][1], aH[mt][2], aH[mt][3], bH0, bH1);
                        mmabf(d[0], d[1], d[2], d[3],
                              aH[mt][0], aH[mt][1], aH[mt][2], aH[mt][3], bL0, bL1);
                        mmabf(d[0], d[1], d[2], d[3],
                              aL[mt][0], aL[mt][1], aL[mt][2], aL[mt][3], bH0, bH1);
                    }
                }
            }
            if (tap < 8)
                stB(smc, ABYTES + (uint32_t)(((tap + 1) & 1) * 20480), rb, tid);
            __syncthreads();
        }
    }

    // epilogue: store + BN2 partials
#pragma unroll
    for (int mt = 0; mt < 2; mt++) {
#pragma unroll
        for (int nt = 0; nt < 8; nt++) {
            int oc0 = n0 + nt * 8 + 2 * tg;
            int pxl = m0 + mt * 16 + g;
            float c0 = acc[mt][nt][0], c1 = acc[mt][nt][1];
            float c2 = acc[mt][nt][2], c3 = acc[mt][nt][3];
            if (oc0 < 100) {
                size_t ob = ((size_t)(b * OC2 + oc0) << 12) + p0 + pxl;
                g_t2[ob] = c0;
                g_t2[ob + 8] = c2;
                if (oc0 + 1 < 100) {
                    g_t2[ob + HW] = c1;
                    g_t2[ob + HW + 8] = c3;
                }
            }
            float s0 = c0 + c2, q0 = fmaf(c0, c0, c2 * c2);
            float s1 = c1 + c3, q1 = fmaf(c1, c1, c3 * c3);
#pragma unroll
            for (int o = 16; o >= 4; o >>= 1) {
                s0 += __shfl_down_sync(0xFFFFFFFFu, s0, o);
                q0 += __shfl_down_sync(0xFFFFFFFFu, q0, o);
                s1 += __shfl_down_sync(0xFFFFFFFFu, s1, o);
                q1 += __shfl_down_sync(0xFFFFFFFFu, q1, o);
            }
            if (lane < 4 && oc0 < 100) {
                atomicAdd(&sAcc[oc0], s0);
                atomicAdd(&qAcc[oc0], q0);
                if (oc0 + 1 < 100) {
                    atomicAdd(&sAcc[oc0 + 1], s1);
                    atomicAdd(&qAcc[oc0 + 1], q1);
                }
            }
        }
    }
    __syncthreads();
    if (tid < 100) {
        int blk = b * 32 + tile;
        g_p2s[blk * 100 + tid] = sAcc[tid];
        g_p2q[blk * 100 + tid] = qAcc[tid];
    }
}

__global__ void k_fin2(const float* __restrict__ gam, const float* __restrict__ bet) {
    const int oc = blockIdx.x, t = threadIdx.x;
    float s = g_p2s[t * 100 + oc], q = g_p2q[t * 100 + oc];
#pragma unroll
    for (int o = 16; o; o >>= 1) {
        s += __shfl_down_sync(0xFFFFFFFFu, s, o);
        q += __shfl_down_sync(0xFFFFFFFFu, q, o);
    }
    __shared__ float ss[8], qq[8];
    if ((t & 31) == 0) { ss[t >> 5] = s; qq[t >> 5] = q; }
    __syncthreads();
    if (t == 0) {
        s = 0.f; q = 0.f;
#pragma unroll
        for (int i = 0; i < 8; i++) { s += ss[i]; q += qq[i]; }
        const float inv = 1.f / 32768.f;
        float m = s * inv, var = fmaf(-m, m, q * inv);
        float k = gam[oc] * rsqrtf(var + EPS);
        g_sc2[oc] = k; g_sh2[oc] = bet[oc] - m * k;
    }
}

// ---------------------------------------------------------------------------
// reassembly (R12 grouped version)
// ---------------------------------------------------------------------------
#define RPOS 140
#define REASM_SMEM ((144 * RPOS + 256 * 25) * 4)

__global__ __launch_bounds__(256, 2) void k_reasm(const float* __restrict__ x,
                                                  float* __restrict__ out) {
    extern __shared__ float sm[];
    float* srcs = sm;
    float* wgt = sm + 144 * RPOS;

    const int b = blockIdx.y;
    const int ti0 = (blockIdx.x >> 3) << 4;
    const int tj0 = (blockIdx.x & 7) << 4;
    const int tid = threadIdx.x;
    const int sy0 = (ti0 >> 1) - 2;
    const int sx0 = (tj0 >> 1) - 2;

#pragma unroll 4
    for (int it = 0; it < 72; it++) {
        int idx = tid + it * 256;
        int c = idx / 144;
        int pos = idx - c * 144;
        int yy = pos / 12;
        int xx = pos - yy * 12;
        int gy = sy0 + yy, gx = sx0 + xx;
        float v = 0.f;
        if ((unsigned)gy < 64u && (unsigned)gx < 64u)
            v = x[((size_t)(b * CIN + c) << 12) + (gy << 6) + gx];
        int p = c >> 1;
        srcs[pos * RPOS + (p >> 4) * 36 + (p & 15) * 2 + (c & 1)] = v;
    }

    {
        int py = tid >> 4, px = tid & 15;
        int gi = ti0 + py, gj = tj0 + px;
        int y0 = gi >> 1, x0 = gj >> 1;
        int sub = ((gi & 1) << 1) | (gj & 1);
        float l[25];
        float mx = -1e30f;
#pragma unroll
        for (int k = 0; k < 25; k++) {
            int ch = (k << 2) + sub;
            float v = fmaf(g_t2[((size_t)(b * OC2 + ch) << 12) + (y0 << 6) + x0],
                           g_sc2[ch], g_sh2[ch]);
            l[k] = v;
            mx = fmaxf(mx, v);
        }
        float s = 0.f;
#pragma unroll
        for (int k = 0; k < 25; k++) { l[k] = __expf(l[k] - mx); s += l[k]; }
        float inv = 1.f / s;
#pragma unroll
        for (int k = 0; k < 25; k++) wgt[tid * 25 + k] = l[k] * inv;
    }
    __syncthreads();

    const int s4 = tid & 3;
    const int quad = tid >> 2;
    const int qy = quad >> 3, qx = quad & 7;
    const int posb = qy * 12 + qx;
    const float* wp0 = &wgt[(2 * qy * 16 + 2 * qx) * 25];
    const int gi0 = ti0 + 2 * qy;
    const int gj = tj0 + 2 * qx;

#pragma unroll 1
    for (int g = 0; g < 2; g++) {
        u64 a[2][2][8];
#pragma unroll
        for (int di = 0; di < 2; di++)
#pragma unroll
            for (int dj = 0; dj < 2; dj++)
#pragma unroll
                for (int j = 0; j < 8; j++) a[di][dj][j] = 0ull;

#pragma unroll 1
        for (int dy = 0; dy < 5; dy++) {
#pragma unroll
            for (int dx = 0; dx < 5; dx++) {
                int k = dy * 5 + dx;
                float w00 = wp0[k], w01 = wp0[25 + k];
                float w10 = wp0[400 + k], w11 = wp0[425 + k];
                u64 W00 = pk(w00, w00), W01 = pk(w01, w01);
                u64 W10 = pk(w10, w10), W11 = pk(w11, w11);
                const ulonglong2* r = (const ulonglong2*)(
                    srcs + (posb + dy * 12 + dx) * RPOS + s4 * 36 + g * 16);
                ulonglong2 q0 = r[0], q1 = r[1], q2 = r[2], q3 = r[3];
                u64 sv[8] = {q0.x, q0.y, q1.x, q1.y, q2.x, q2.y, q3.x, q3.y};
#pragma unroll
                for (int j = 0; j < 8; j++) {
                    fma2(a[0][0][j], W00, sv[j]);
                    fma2(a[0][1][j], W01, sv[j]);
                    fma2(a[1][0][j], W10, sv[j]);
                    fma2(a[1][1][j], W11, sv[j]);
                }
            }
        }

#pragma unroll
        for (int j = 0; j < 8; j++) {
            int p = s4 * 16 + g * 8 + j;
            int c = 2 * p;
#pragma unroll
            for (int di = 0; di < 2; di++) {
                float e0, h0, e1, h1;
                unpk(a[di][0][j], e0, h0);
                unpk(a[di][1][j], e1, h1);
                size_t ob = (((size_t)(b * CIN + c) << 7) + gi0 + di) * 128 + gj;
                *(float2*)&out[ob] = make_float2(e0, e1);
                *(float2*)&out[ob + 16384] = make_float2(h0, h1);
            }
        }
    }
}

// ---------------------------------------------------------------------------
extern "C" void kernel_launch(void* const* d_in, const int* in_sizes, int n_in,
                              void* d_out, int out_size) {
    const float* x      = (const float*)d_in[0];
    const float* comp_w = (const float*)d_in[1];
    const float* comp_g = (const float*)d_in[2];
    const float* comp_b = (const float*)d_in[3];
    const float* enc_w  = (const float*)d_in[4];
    const float* enc_g  = (const float*)d_in[5];
    const float* enc_b  = (const float*)d_in[6];
    float* out = (float*)d_out;

    cudaFuncSetAttribute(k_conv3mma, cudaFuncAttributeMaxDynamicSharedMemorySize, C3_SMEM);
    cudaFuncSetAttribute(k_reasm, cudaFuncAttributeMaxDynamicSharedMemorySize, REASM_SMEM);

    k_prep<<<320, 256>>>(comp_w, enc_w);                 // 0
    k_conv1<<<dim3(16, B), 256>>>(x);                    // 1
    k_act<<<dim3(32, B), 256>>>(comp_g, comp_b);         // 2
    k_conv3mma<<<dim3(32, B), 256, C3_SMEM>>>();         // 3  <- ncu slot
    k_fin2<<<OC2, 256>>>(enc_g, enc_b);                  // 4
    k_reasm<<<dim3(64, B), 256, REASM_SMEM>>>(x, out);   // 5
}

// round 16
// speedup vs baseline: 1.4927x; 1.0445x over previous
#include <cuda_runtime.h>
#include <cuda_bf16.h>
#include <cstdint>
#include <math.h>

// ---------------------------------------------------------------------------
// CARAFE fp32.  Round 16: conv3mma A-resident window (R15) + single-buffer
// per-tap B staging (no reg pipeline) -> regs back under 128 for 2 CTA/SM.
// ---------------------------------------------------------------------------

#define B 8
#define CIN 128
#define MID 64
#define OC2 100
#define HW 4096
#define EPS 1e-5f

typedef unsigned long long u64;
typedef unsigned short u16;

__device__ __forceinline__ u64 pk(float lo, float hi) {
    u64 r; asm("mov.b64 %0,{%1,%2};" : "=l"(r) : "f"(lo), "f"(hi)); return r;
}
__device__ __forceinline__ void fma2(u64& d, u64 a, u64 b) {
    asm("fma.rn.f32x2 %0,%1,%2,%0;" : "+l"(d) : "l"(a), "l"(b));
}
__device__ __forceinline__ u64 add2(u64 a, u64 b) {
    u64 r; asm("add.rn.f32x2 %0,%1,%2;" : "=l"(r) : "l"(a), "l"(b)); return r;
}
__device__ __forceinline__ void unpk(u64 a, float& lo, float& hi) {
    asm("mov.b64 {%0,%1},%2;" : "=f"(lo), "=f"(hi) : "l"(a));
}
__device__ __forceinline__ u16 bfbits(float v) {
    __nv_bfloat16 h = __float2bfloat16(v);
    return *reinterpret_cast<u16*>(&h);
}
__device__ __forceinline__ float bf2f(u16 s) {
    __nv_bfloat16 h = *reinterpret_cast<__nv_bfloat16*>(&s);
    return __bfloat162float(h);
}
__device__ __forceinline__ uint32_t smem_u32(const void* p) {
    uint32_t a;
    asm("{ .reg .u64 t; cvta.to.shared.u64 t, %1; cvt.u32.u64 %0, t; }"
        : "=r"(a) : "l"(p));
    return a;
}

__device__ __forceinline__ void mmabf(float& d0, float& d1, float& d2, float& d3,
                                      uint32_t a0, uint32_t a1, uint32_t a2, uint32_t a3,
                                      uint32_t b0, uint32_t b1) {
    asm volatile(
        "mma.sync.aligned.m16n8k16.row.col.f32.bf16.bf16.f32 "
        "{%0,%1,%2,%3},{%4,%5,%6,%7},{%8,%9},{%0,%1,%2,%3};"
        : "+f"(d0), "+f"(d1), "+f"(d2), "+f"(d3)
        : "r"(a0), "r"(a1), "r"(a2), "r"(a3), "r"(b0), "r"(b1));
}
__device__ __forceinline__ void lm4(uint32_t& r0, uint32_t& r1, uint32_t& r2,
                                    uint32_t& r3, uint32_t a) {
    asm volatile("ldmatrix.sync.aligned.m8n8.x4.shared.b16 {%0,%1,%2,%3},[%4];"
                 : "=r"(r0), "=r"(r1), "=r"(r2), "=r"(r3) : "r"(a));
}
__device__ __forceinline__ void lm2(uint32_t& r0, uint32_t& r1, uint32_t a) {
    asm volatile("ldmatrix.sync.aligned.m8n8.x2.shared.b16 {%0,%1},[%2];"
                 : "=r"(r0), "=r"(r1) : "r"(a));
}

// scratch
__device__ __align__(16) float g_t1[B * MID * HW];
__device__ __align__(16) float g_t2[B * OC2 * HW];
__device__ float g_sc2[OC2], g_sh2[OC2];
__device__ __align__(16) float g_p1s[128 * 64], g_p1q[128 * 64];
__device__ __align__(16) float g_p2s[256 * 100], g_p2q[256 * 100];
__device__ __align__(16) float g_w1T[128 * 64];                 // [cc][oc]
__device__ __align__(16) u16 g_aH[B * HW * 64], g_aL[B * HW * 64];  // [b][px][c]
__device__ __align__(16) u16 g_wH[18 * 4096], g_wL[18 * 4096];  // [chunk][oc 128][k 32]

__device__ __forceinline__ void wred2(u64& s, u64& q) {
#pragma unroll
    for (int o = 16; o; o >>= 1) {
        s = add2(s, __shfl_down_sync(0xFFFFFFFFu, s, o));
        q = add2(q, __shfl_down_sync(0xFFFFFFFFu, q, o));
    }
}

// ---------------------------------------------------------------------------
// prep
// ---------------------------------------------------------------------------
__global__ void k_prep(const float* __restrict__ cw, const float* __restrict__ ew) {
    int idx = blockIdx.x * 256 + threadIdx.x;
    if (idx < 18 * 4096) {
        int chunk = idx >> 12;
        int r = idx & 4095;
        int oc = r >> 5, k = r & 31;
        int tap = chunk >> 1, half = chunk & 1;
        float v = 0.f;
        if (oc < 100) v = ew[(oc * 64 + half * 32 + k) * 9 + tap];
        u16 hb = bfbits(v);
        float hf = bf2f(hb);
        g_wH[idx] = hb;
        g_wL[idx] = bfbits(v - hf);
    } else if (idx < 18 * 4096 + 8192) {
        int j = idx - 18 * 4096;
        int cc = j >> 6, oc = j & 63;
        g_w1T[j] = cw[oc * 128 + cc];
    }
}

// ---------------------------------------------------------------------------
// conv1x1 (unchanged): grid(16,8) x 256.
// ---------------------------------------------------------------------------
__global__ void k_conv1(const float* __restrict__ x) {
    __shared__ float xs[32][256];
    __shared__ __align__(16) float ws1[32][64];
    __shared__ u64 r_s[8][8], r_q[8][8];
    const int b = blockIdx.y;
    const int p0 = blockIdx.x * 256;
    const int tid = threadIdx.x;
    const int pixg = tid & 63;
    const int ocg = tid >> 6;

    u64 acc[8][4];
#pragma unroll
    for (int p = 0; p < 8; p++)
#pragma unroll
        for (int j = 0; j < 4; j++) acc[p][j] = 0ull;

    for (int c0 = 0; c0 < CIN; c0 += 32) {
        __syncthreads();
#pragma unroll 4
        for (int j = 0; j < 32; j++)
            xs[j][tid] = x[((size_t)(b * CIN + c0 + j) << 12) + p0 + tid];
#pragma unroll
        for (int j = 0; j < 8; j++) {
            int idx = j * 256 + tid;
            int oc = idx & 63, cc = idx >> 6;
            ws1[cc][oc] = g_w1T[(c0 + cc) * 64 + oc];
        }
        __syncthreads();
#pragma unroll 4
        for (int cc = 0; cc < 32; cc++) {
            float4 xv = *(const float4*)&xs[cc][pixg * 4];
            u64 P0 = pk(xv.x, xv.x), P1 = pk(xv.y, xv.y);
            u64 P2 = pk(xv.z, xv.z), P3 = pk(xv.w, xv.w);
            const u64* wp = (const u64*)&ws1[cc][ocg * 16];
#pragma unroll
            for (int p = 0; p < 8; p++) {
                u64 w = wp[p];
                fma2(acc[p][0], w, P0);
                fma2(acc[p][1], w, P1);
                fma2(acc[p][2], w, P2);
                fma2(acc[p][3], w, P3);
            }
        }
    }
    const int lane = tid & 31, wid = tid >> 5;
#pragma unroll
    for (int p = 0; p < 8; p++) {
        int oce = ocg * 16 + 2 * p;
        float e0, o0, e1, o1, e2, o2, e3, o3;
        unpk(acc[p][0], e0, o0); unpk(acc[p][1], e1, o1);
        unpk(acc[p][2], e2, o2); unpk(acc[p][3], e3, o3);
        *(float4*)&g_t1[((size_t)(b * MID + oce) << 12) + p0 + pixg * 4] =
            make_float4(e0, e1, e2, e3);
        *(float4*)&g_t1[((size_t)(b * MID + oce + 1) << 12) + p0 + pixg * 4] =
            make_float4(o0, o1, o2, o3);
        u64 s = add2(add2(acc[p][0], acc[p][1]), add2(acc[p][2], acc[p][3]));
        u64 q = 0ull;
        fma2(q, acc[p][0], acc[p][0]); fma2(q, acc[p][1], acc[p][1]);
        fma2(q, acc[p][2], acc[p][2]); fma2(q, acc[p][3], acc[p][3]);
        wred2(s, q);
        if (lane == 0) { r_s[wid][p] = s; r_q[wid][p] = q; }
    }
    __syncthreads();
    if (tid < 32) {
        int g = tid >> 3, p = tid & 7;
        u64 s = add2(r_s[2 * g][p], r_s[2 * g + 1][p]);
        u64 q = add2(r_q[2 * g][p], r_q[2 * g + 1][p]);
        int blk = b * 16 + blockIdx.x;
        *(u64*)&g_p1s[blk * 64 + 2 * (g * 8 + p)] = s;
        *(u64*)&g_p1q[blk * 64 + 2 * (g * 8 + p)] = q;
    }
}

// ---------------------------------------------------------------------------
// act (fin1 fused): grid(32,8) x 256; block = 2 rows.
// ---------------------------------------------------------------------------
__global__ void k_act(const float* __restrict__ gam, const float* __restrict__ bet) {
    __shared__ float ts[64][65];
    __shared__ float ps[4][64], pq[4][64];
    __shared__ float sc[64], sh[64];
    const int y0 = blockIdx.x * 2, b = blockIdx.y;
    const int tid = threadIdx.x;

    {
        int c = tid & 63, gp = tid >> 6;
        float s = 0.f, q = 0.f;
#pragma unroll 8
        for (int i = 0; i < 32; i++) {
            int blk = gp * 32 + i;
            s += g_p1s[blk * 64 + c];
            q += g_p1q[blk * 64 + c];
        }
        ps[gp][c] = s; pq[gp][c] = q;
    }
    __syncthreads();
    if (tid < 64) {
        float s = ps[0][tid] + ps[1][tid] + ps[2][tid] + ps[3][tid];
        float q = pq[0][tid] + pq[1][tid] + pq[2][tid] + pq[3][tid];
        const float inv = 1.f / 32768.f;
        float m = s * inv, var = fmaf(-m, m, q * inv);
        float k = gam[tid] * rsqrtf(var + EPS);
        sc[tid] = k; sh[tid] = bet[tid] - m * k;
    }

#pragma unroll 1
    for (int ry = 0; ry < 2; ry++) {
        const int y = y0 + ry;
        __syncthreads();
#pragma unroll
        for (int it = 0; it < 4; it++) {
            int idx = it * 256 + tid;
            int c = idx >> 4, x4 = idx & 15;
            float4 v = *(const float4*)&g_t1[((size_t)(b * MID + c) << 12)
                                             + (y << 6) + x4 * 4];
            float z0 = fmaf(v.x, sc[c], sh[c]);
            float z1 = fmaf(v.y, sc[c], sh[c]);
            float z2 = fmaf(v.z, sc[c], sh[c]);
            float z3 = fmaf(v.w, sc[c], sh[c]);
            ts[c][x4 * 4 + 0] = z0 * (1.f / (1.f + __expf(-z0)));
            ts[c][x4 * 4 + 1] = z1 * (1.f / (1.f + __expf(-z1)));
            ts[c][x4 * 4 + 2] = z2 * (1.f / (1.f + __expf(-z2)));
            ts[c][x4 * 4 + 3] = z3 * (1.f / (1.f + __expf(-z3)));
        }
        __syncthreads();
        const size_t rowbase = (size_t)((b << 6) + y) << 12;
        uint32_t* dH = (uint32_t*)(g_aH + rowbase);
        uint32_t* dL = (uint32_t*)(g_aL + rowbase);
#pragma unroll
        for (int it = 0; it < 8; it++) {
            int idx = it * 256 + tid;
            int xx = idx >> 5, cp = idx & 31;
            float v0 = ts[2 * cp][xx], v1 = ts[2 * cp + 1][xx];
            u16 h0 = bfbits(v0), h1 = bfbits(v1);
            u16 l0 = bfbits(v0 - bf2f(h0)), l1 = bfbits(v1 - bf2f(h1));
            dH[xx * 32 + cp] = (uint32_t)h0 | ((uint32_t)h1 << 16);
            dL[xx * 32 + cp] = (uint32_t)l0 | ((uint32_t)l1 << 16);
        }
    }
}

// ---------------------------------------------------------------------------
// conv3 v3: A window resident per half; B single buffer staged per tap.
// smem (bytes): A [arr 2][px 264][80] @0/21120 (42240); B [arr 2][oc 128][80] @42240
// total 62720 -> 2 CTA/SM (if regs <= 128).
// ---------------------------------------------------------------------------
#define ABYTES 42240
#define C3_SMEM (ABYTES + 20480 + 256)

__global__ __launch_bounds__(256) void k_conv3mma() {
    extern __shared__ __align__(16) char smc[];
    __shared__ float sAcc[128], qAcc[128];
    const uint32_t sb = smem_u32(smc);
    const int tid = threadIdx.x;
    const int tile = blockIdx.x, b = blockIdx.y;
    const int p0 = tile * 128;
    const int lane = tid & 31, wid = tid >> 5;
    const int g = lane >> 2, tg = lane & 3;
    const int wm = wid >> 1, wn = wid & 1;
    const int m0 = wm * 32, n0 = wn * 64;

    if (tid < 128) { sAcc[tid] = 0.f; qAcc[tid] = 0.f; }

    float acc[2][8][4];
#pragma unroll
    for (int mt = 0; mt < 2; mt++)
#pragma unroll
        for (int nt = 0; nt < 8; nt++)
#pragma unroll
            for (int j = 0; j < 4; j++) acc[mt][nt][j] = 0.f;

    // per-lane ldmatrix address components
    uint32_t aoffm[2];
#pragma unroll
    for (int mt = 0; mt < 2; mt++) {
        int pxl = m0 + mt * 16 + (lane & 15);
        int ty = pxl >> 6, xx = pxl & 63;
        aoffm[mt] = (uint32_t)(((ty + 1) * 66 + xx + 1) * 80) + ((lane >> 4) << 4);
    }
    const uint32_t blane = (uint32_t)((n0 + (lane & 7)) * 80) + (((lane >> 3) & 3) << 4);

#pragma unroll 1
    for (int half = 0; half < 2; half++) {
        __syncthreads();   // prior compute done before A overwrite
        // stage A window [2 arr][4 rows][66 cols] for this half
        for (int idx = tid; idx < 2112; idx += 256) {
            int arr = idx / 1056;
            int j = idx - arr * 1056;
            int px = j >> 2, u = j & 3;
            int r = px / 66, cc = px - r * 66;
            int gy = tile * 2 - 1 + r, gx = cc - 1;
            float4 v = make_float4(0.f, 0.f, 0.f, 0.f);
            if ((unsigned)gy < 64u && (unsigned)gx < 64u) {
                const u16* src = (arr ? g_aL : g_aH) +
                    ((size_t)(b << 12) + (gy << 6) + gx) * 64 + half * 32 + u * 8;
                v = *(const float4*)src;
            }
            *(float4*)(smc + arr * 21120 + px * 80 + u * 16) = v;
        }

#pragma unroll 1
        for (int tap = 0; tap < 9; tap++) {
            if (tap > 0) __syncthreads();      // prev compute done reading B
            // stage B for chunk = tap*2 + half (16KB)
            {
                const int chunk = tap * 2 + half;
#pragma unroll
                for (int it = 0; it < 4; it++) {
                    int j = it * 256 + tid;
                    int arr = j >> 9, jb = j & 511;
                    int oc = jb >> 2, u = jb & 3;
                    const u16* src = (arr ? g_wL : g_wH) + (chunk << 12) + oc * 32 + u * 8;
                    *(float4*)(smc + ABYTES + arr * 10240 + oc * 80 + u * 16) =
                        *(const float4*)src;
                }
            }
            __syncthreads();

            const int dyq = tap / 3;
            const int tapoff = ((dyq - 1) * 66 + (tap - 3 * dyq - 1)) * 80;

#pragma unroll
            for (int ks = 0; ks < 2; ks++) {
                const uint32_t ko = ks * 32;
                uint32_t aH[2][4], aL[2][4];
#pragma unroll
                for (int mt = 0; mt < 2; mt++) {
                    uint32_t a = sb + aoffm[mt] + tapoff + ko;
                    lm4(aH[mt][0], aH[mt][1], aH[mt][2], aH[mt][3], a);
                    lm4(aL[mt][0], aL[mt][1], aL[mt][2], aL[mt][3], a + 21120);
                }
#pragma unroll
                for (int nt = 0; nt < 8; nt++) {
                    uint32_t ba = sb + ABYTES + blane + nt * 640 + ko;
                    uint32_t bH0, bH1, bL0, bL1;
                    lm2(bH0, bH1, ba);
                    lm2(bL0, bL1, ba + 10240);
#pragma unroll
                    for (int mt = 0; mt < 2; mt++) {
                        float* d = acc[mt][nt];
                        mmabf(d[0], d[1], d[2], d[3],
                              aH[mt][0], aH[mt][1], aH[mt][2], aH[mt][3], bH0, bH1);
                        mmabf(d[0], d[1], d[2], d[3],
                              aH[mt][0], aH[mt][1], aH[mt][2], aH[mt][3], bL0, bL1);
                        mmabf(d[0], d[1], d[2], d[3],
                              aL[mt][0], aL[mt][1], aL[mt][2], aL[mt][3], bH0, bH1);
                    }
                }
            }
        }
        __syncthreads();   // compute done before next-half A restage
    }

    // epilogue: store + BN2 partials
#pragma unroll
    for (int mt = 0; mt < 2; mt++) {
#pragma unroll
        for (int nt = 0; nt < 8; nt++) {
            int oc0 = n0 + nt * 8 + 2 * tg;
            int pxl = m0 + mt * 16 + g;
            float c0 = acc[mt][nt][0], c1 = acc[mt][nt][1];
            float c2 = acc[mt][nt][2], c3 = acc[mt][nt][3];
            if (oc0 < 100) {
                size_t ob = ((size_t)(b * OC2 + oc0) << 12) + p0 + pxl;
                g_t2[ob] = c0;
                g_t2[ob + 8] = c2;
                if (oc0 + 1 < 100) {
                    g_t2[ob + HW] = c1;
                    g_t2[ob + HW + 8] = c3;
                }
            }
            float s0 = c0 + c2, q0 = fmaf(c0, c0, c2 * c2);
            float s1 = c1 + c3, q1 = fmaf(c1, c1, c3 * c3);
#pragma unroll
            for (int o = 16; o >= 4; o >>= 1) {
                s0 += __shfl_down_sync(0xFFFFFFFFu, s0, o);
                q0 += __shfl_down_sync(0xFFFFFFFFu, q0, o);
                s1 += __shfl_down_sync(0xFFFFFFFFu, s1, o);
                q1 += __shfl_down_sync(0xFFFFFFFFu, q1, o);
            }
            if (lane < 4 && oc0 < 100) {
                atomicAdd(&sAcc[oc0], s0);
                atomicAdd(&qAcc[oc0], q0);
                if (oc0 + 1 < 100) {
                    atomicAdd(&sAcc[oc0 + 1], s1);
                    atomicAdd(&qAcc[oc0 + 1], q1);
                }
            }
        }
    }
    __syncthreads();
    if (tid < 100) {
        int blk = b * 32 + tile;
        g_p2s[blk * 100 + tid] = sAcc[tid];
        g_p2q[blk * 100 + tid] = qAcc[tid];
    }
}

__global__ void k_fin2(const float* __restrict__ gam, const float* __restrict__ bet) {
    const int oc = blockIdx.x, t = threadIdx.x;
    float s = g_p2s[t * 100 + oc], q = g_p2q[t * 100 + oc];
#pragma unroll
    for (int o = 16; o; o >>= 1) {
        s += __shfl_down_sync(0xFFFFFFFFu, s, o);
        q += __shfl_down_sync(0xFFFFFFFFu, q, o);
    }
    __shared__ float ss[8], qq[8];
    if ((t & 31) == 0) { ss[t >> 5] = s; qq[t >> 5] = q; }
    __syncthreads();
    if (t == 0) {
        s = 0.f; q = 0.f;
#pragma unroll
        for (int i = 0; i < 8; i++) { s += ss[i]; q += qq[i]; }
        const float inv = 1.f / 32768.f;
        float m = s * inv, var = fmaf(-m, m, q * inv);
        float k = gam[oc] * rsqrtf(var + EPS);
        g_sc2[oc] = k; g_sh2[oc] = bet[oc] - m * k;
    }
}

// ---------------------------------------------------------------------------
// reassembly (R12 grouped version)
// ---------------------------------------------------------------------------
#define RPOS 140
#define REASM_SMEM ((144 * RPOS + 256 * 25) * 4)

__global__ __launch_bounds__(256, 2) void k_reasm(const float* __restrict__ x,
                                                  float* __restrict__ out) {
    extern __shared__ float sm[];
    float* srcs = sm;
    float* wgt = sm + 144 * RPOS;

    const int b = blockIdx.y;
    const int ti0 = (blockIdx.x >> 3) << 4;
    const int tj0 = (blockIdx.x & 7) << 4;
    const int tid = threadIdx.x;
    const int sy0 = (ti0 >> 1) - 2;
    const int sx0 = (tj0 >> 1) - 2;

#pragma unroll 4
    for (int it = 0; it < 72; it++) {
        int idx = tid + it * 256;
        int c = idx / 144;
        int pos = idx - c * 144;
        int yy = pos / 12;
        int xx = pos - yy * 12;
        int gy = sy0 + yy, gx = sx0 + xx;
        float v = 0.f;
        if ((unsigned)gy < 64u && (unsigned)gx < 64u)
            v = x[((size_t)(b * CIN + c) << 12) + (gy << 6) + gx];
        int p = c >> 1;
        srcs[pos * RPOS + (p >> 4) * 36 + (p & 15) * 2 + (c & 1)] = v;
    }

    {
        int py = tid >> 4, px = tid & 15;
        int gi = ti0 + py, gj = tj0 + px;
        int y0 = gi >> 1, x0 = gj >> 1;
        int sub = ((gi & 1) << 1) | (gj & 1);
        float l[25];
        float mx = -1e30f;
#pragma unroll
        for (int k = 0; k < 25; k++) {
            int ch = (k << 2) + sub;
            float v = fmaf(g_t2[((size_t)(b * OC2 + ch) << 12) + (y0 << 6) + x0],
                           g_sc2[ch], g_sh2[ch]);
            l[k] = v;
            mx = fmaxf(mx, v);
        }
        float s = 0.f;
#pragma unroll
        for (int k = 0; k < 25; k++) { l[k] = __expf(l[k] - mx); s += l[k]; }
        float inv = 1.f / s;
#pragma unroll
        for (int k = 0; k < 25; k++) wgt[tid * 25 + k] = l[k] * inv;
    }
    __syncthreads();

    const int s4 = tid & 3;
    const int quad = tid >> 2;
    const int qy = quad >> 3, qx = quad & 7;
    const int posb = qy * 12 + qx;
    const float* wp0 = &wgt[(2 * qy * 16 + 2 * qx) * 25];
    const int gi0 = ti0 + 2 * qy;
    const int gj = tj0 + 2 * qx;

#pragma unroll 1
    for (int g = 0; g < 2; g++) {
        u64 a[2][2][8];
#pragma unroll
        for (int di = 0; di < 2; di++)
#pragma unroll
            for (int dj = 0; dj < 2; dj++)
#pragma unroll
                for (int j = 0; j < 8; j++) a[di][dj][j] = 0ull;

#pragma unroll 1
        for (int dy = 0; dy < 5; dy++) {
#pragma unroll
            for (int dx = 0; dx < 5; dx++) {
                int k = dy * 5 + dx;
                float w00 = wp0[k], w01 = wp0[25 + k];
                float w10 = wp0[400 + k], w11 = wp0[425 + k];
                u64 W00 = pk(w00, w00), W01 = pk(w01, w01);
                u64 W10 = pk(w10, w10), W11 = pk(w11, w11);
                const ulonglong2* r = (const ulonglong2*)(
                    srcs + (posb + dy * 12 + dx) * RPOS + s4 * 36 + g * 16);
                ulonglong2 q0 = r[0], q1 = r[1], q2 = r[2], q3 = r[3];
                u64 sv[8] = {q0.x, q0.y, q1.x, q1.y, q2.x, q2.y, q3.x, q3.y};
#pragma unroll
                for (int j = 0; j < 8; j++) {
                    fma2(a[0][0][j], W00, sv[j]);
                    fma2(a[0][1][j], W01, sv[j]);
                    fma2(a[1][0][j], W10, sv[j]);
                    fma2(a[1][1][j], W11, sv[j]);
                }
            }
        }

#pragma unroll
        for (int j = 0; j < 8; j++) {
            int p = s4 * 16 + g * 8 + j;
            int c = 2 * p;
#pragma unroll
            for (int di = 0; di < 2; di++) {
                float e0, h0, e1, h1;
                unpk(a[di][0][j], e0, h0);
                unpk(a[di][1][j], e1, h1);
                size_t ob = (((size_t)(b * CIN + c) << 7) + gi0 + di) * 128 + gj;
                *(float2*)&out[ob] = make_float2(e0, e1);
                *(float2*)&out[ob + 16384] = make_float2(h0, h1);
            }
        }
    }
}

// ---------------------------------------------------------------------------
extern "C" void kernel_launch(void* const* d_in, const int* in_sizes, int n_in,
                              void* d_out, int out_size) {
    const float* x      = (const float*)d_in[0];
    const float* comp_w = (const float*)d_in[1];
    const float* comp_g = (const float*)d_in[2];
    const float* comp_b = (const float*)d_in[3];
    const float* enc_w  = (const float*)d_in[4];
    const float* enc_g  = (const float*)d_in[5];
    const float* enc_b  = (const float*)d_in[6];
    float* out = (float*)d_out;

    cudaFuncSetAttribute(k_conv3mma, cudaFuncAttributeMaxDynamicSharedMemorySize, C3_SMEM);
    cudaFuncSetAttribute(k_reasm, cudaFuncAttributeMaxDynamicSharedMemorySize, REASM_SMEM);

    k_prep<<<320, 256>>>(comp_w, enc_w);                 // 0
    k_conv1<<<dim3(16, B), 256>>>(x);                    // 1
    k_act<<<dim3(32, B), 256>>>(comp_g, comp_b);         // 2
    k_conv3mma<<<dim3(32, B), 256, C3_SMEM>>>();         // 3  <- ncu slot
    k_fin2<<<OC2, 256>>>(enc_g, enc_b);                  // 4
    k_reasm<<<dim3(64, B), 256, REASM_SMEM>>>(x, out);   // 5
}

// round 17
// speedup vs baseline: 1.5145x; 1.0146x over previous
#include <cuda_runtime.h>
#include <cuda_bf16.h>
#include <cstdint>
#include <math.h>

// ---------------------------------------------------------------------------
// CARAFE fp32.  Round 17: reasm LDS bank-conflict fix (RPOS 140->144: lane
// unit addr 4qx+9s4 mod 32 now bijective); conv3 mma chain interleaved.
// ---------------------------------------------------------------------------

#define B 8
#define CIN 128
#define MID 64
#define OC2 100
#define HW 4096
#define EPS 1e-5f

typedef unsigned long long u64;
typedef unsigned short u16;

__device__ __forceinline__ u64 pk(float lo, float hi) {
    u64 r; asm("mov.b64 %0,{%1,%2};" : "=l"(r) : "f"(lo), "f"(hi)); return r;
}
__device__ __forceinline__ void fma2(u64& d, u64 a, u64 b) {
    asm("fma.rn.f32x2 %0,%1,%2,%0;" : "+l"(d) : "l"(a), "l"(b));
}
__device__ __forceinline__ u64 add2(u64 a, u64 b) {
    u64 r; asm("add.rn.f32x2 %0,%1,%2;" : "=l"(r) : "l"(a), "l"(b)); return r;
}
__device__ __forceinline__ void unpk(u64 a, float& lo, float& hi) {
    asm("mov.b64 {%0,%1},%2;" : "=f"(lo), "=f"(hi) : "l"(a));
}
__device__ __forceinline__ u16 bfbits(float v) {
    __nv_bfloat16 h = __float2bfloat16(v);
    return *reinterpret_cast<u16*>(&h);
}
__device__ __forceinline__ float bf2f(u16 s) {
    __nv_bfloat16 h = *reinterpret_cast<__nv_bfloat16*>(&s);
    return __bfloat162float(h);
}
__device__ __forceinline__ uint32_t smem_u32(const void* p) {
    uint32_t a;
    asm("{ .reg .u64 t; cvta.to.shared.u64 t, %1; cvt.u32.u64 %0, t; }"
        : "=r"(a) : "l"(p));
    return a;
}

__device__ __forceinline__ void mmabf(float& d0, float& d1, float& d2, float& d3,
                                      uint32_t a0, uint32_t a1, uint32_t a2, uint32_t a3,
                                      uint32_t b0, uint32_t b1) {
    asm volatile(
        "mma.sync.aligned.m16n8k16.row.col.f32.bf16.bf16.f32 "
        "{%0,%1,%2,%3},{%4,%5,%6,%7},{%8,%9},{%0,%1,%2,%3};"
        : "+f"(d0), "+f"(d1), "+f"(d2), "+f"(d3)
        : "r"(a0), "r"(a1), "r"(a2), "r"(a3), "r"(b0), "r"(b1));
}
__device__ __forceinline__ void lm4(uint32_t& r0, uint32_t& r1, uint32_t& r2,
                                    uint32_t& r3, uint32_t a) {
    asm volatile("ldmatrix.sync.aligned.m8n8.x4.shared.b16 {%0,%1,%2,%3},[%4];"
                 : "=r"(r0), "=r"(r1), "=r"(r2), "=r"(r3) : "r"(a));
}
__device__ __forceinline__ void lm2(uint32_t& r0, uint32_t& r1, uint32_t a) {
    asm volatile("ldmatrix.sync.aligned.m8n8.x2.shared.b16 {%0,%1},[%2];"
                 : "=r"(r0), "=r"(r1) : "r"(a));
}

// scratch
__device__ __align__(16) float g_t1[B * MID * HW];
__device__ __align__(16) float g_t2[B * OC2 * HW];
__device__ float g_sc2[OC2], g_sh2[OC2];
__device__ __align__(16) float g_p1s[128 * 64], g_p1q[128 * 64];
__device__ __align__(16) float g_p2s[256 * 100], g_p2q[256 * 100];
__device__ __align__(16) float g_w1T[128 * 64];                 // [cc][oc]
__device__ __align__(16) u16 g_aH[B * HW * 64], g_aL[B * HW * 64];  // [b][px][c]
__device__ __align__(16) u16 g_wH[18 * 4096], g_wL[18 * 4096];  // [chunk][oc 128][k 32]

__device__ __forceinline__ void wred2(u64& s, u64& q) {
#pragma unroll
    for (int o = 16; o; o >>= 1) {
        s = add2(s, __shfl_down_sync(0xFFFFFFFFu, s, o));
        q = add2(q, __shfl_down_sync(0xFFFFFFFFu, q, o));
    }
}

// ---------------------------------------------------------------------------
// prep
// ---------------------------------------------------------------------------
__global__ void k_prep(const float* __restrict__ cw, const float* __restrict__ ew) {
    int idx = blockIdx.x * 256 + threadIdx.x;
    if (idx < 18 * 4096) {
        int chunk = idx >> 12;
        int r = idx & 4095;
        int oc = r >> 5, k = r & 31;
        int tap = chunk >> 1, half = chunk & 1;
        float v = 0.f;
        if (oc < 100) v = ew[(oc * 64 + half * 32 + k) * 9 + tap];
        u16 hb = bfbits(v);
        float hf = bf2f(hb);
        g_wH[idx] = hb;
        g_wL[idx] = bfbits(v - hf);
    } else if (idx < 18 * 4096 + 8192) {
        int j = idx - 18 * 4096;
        int cc = j >> 6, oc = j & 63;
        g_w1T[j] = cw[oc * 128 + cc];
    }
}

// ---------------------------------------------------------------------------
// conv1x1 (unchanged): grid(16,8) x 256.
// ---------------------------------------------------------------------------
__global__ void k_conv1(const float* __restrict__ x) {
    __shared__ float xs[32][256];
    __shared__ __align__(16) float ws1[32][64];
    __shared__ u64 r_s[8][8], r_q[8][8];
    const int b = blockIdx.y;
    const int p0 = blockIdx.x * 256;
    const int tid = threadIdx.x;
    const int pixg = tid & 63;
    const int ocg = tid >> 6;

    u64 acc[8][4];
#pragma unroll
    for (int p = 0; p < 8; p++)
#pragma unroll
        for (int j = 0; j < 4; j++) acc[p][j] = 0ull;

    for (int c0 = 0; c0 < CIN; c0 += 32) {
        __syncthreads();
#pragma unroll 4
        for (int j = 0; j < 32; j++)
            xs[j][tid] = x[((size_t)(b * CIN + c0 + j) << 12) + p0 + tid];
#pragma unroll
        for (int j = 0; j < 8; j++) {
            int idx = j * 256 + tid;
            int oc = idx & 63, cc = idx >> 6;
            ws1[cc][oc] = g_w1T[(c0 + cc) * 64 + oc];
        }
        __syncthreads();
#pragma unroll 4
        for (int cc = 0; cc < 32; cc++) {
            float4 xv = *(const float4*)&xs[cc][pixg * 4];
            u64 P0 = pk(xv.x, xv.x), P1 = pk(xv.y, xv.y);
            u64 P2 = pk(xv.z, xv.z), P3 = pk(xv.w, xv.w);
            const u64* wp = (const u64*)&ws1[cc][ocg * 16];
#pragma unroll
            for (int p = 0; p < 8; p++) {
                u64 w = wp[p];
                fma2(acc[p][0], w, P0);
                fma2(acc[p][1], w, P1);
                fma2(acc[p][2], w, P2);
                fma2(acc[p][3], w, P3);
            }
        }
    }
    const int lane = tid & 31, wid = tid >> 5;
#pragma unroll
    for (int p = 0; p < 8; p++) {
        int oce = ocg * 16 + 2 * p;
        float e0, o0, e1, o1, e2, o2, e3, o3;
        unpk(acc[p][0], e0, o0); unpk(acc[p][1], e1, o1);
        unpk(acc[p][2], e2, o2); unpk(acc[p][3], e3, o3);
        *(float4*)&g_t1[((size_t)(b * MID + oce) << 12) + p0 + pixg * 4] =
            make_float4(e0, e1, e2, e3);
        *(float4*)&g_t1[((size_t)(b * MID + oce + 1) << 12) + p0 + pixg * 4] =
            make_float4(o0, o1, o2, o3);
        u64 s = add2(add2(acc[p][0], acc[p][1]), add2(acc[p][2], acc[p][3]));
        u64 q = 0ull;
        fma2(q, acc[p][0], acc[p][0]); fma2(q, acc[p][1], acc[p][1]);
        fma2(q, acc[p][2], acc[p][2]); fma2(q, acc[p][3], acc[p][3]);
        wred2(s, q);
        if (lane == 0) { r_s[wid][p] = s; r_q[wid][p] = q; }
    }
    __syncthreads();
    if (tid < 32) {
        int g = tid >> 3, p = tid & 7;
        u64 s = add2(r_s[2 * g][p], r_s[2 * g + 1][p]);
        u64 q = add2(r_q[2 * g][p], r_q[2 * g + 1][p]);
        int blk = b * 16 + blockIdx.x;
        *(u64*)&g_p1s[blk * 64 + 2 * (g * 8 + p)] = s;
        *(u64*)&g_p1q[blk * 64 + 2 * (g * 8 + p)] = q;
    }
}

// ---------------------------------------------------------------------------
// act (fin1 fused): grid(32,8) x 256; block = 2 rows.
// ---------------------------------------------------------------------------
__global__ void k_act(const float* __restrict__ gam, const float* __restrict__ bet) {
    __shared__ float ts[64][65];
    __shared__ float ps[4][64], pq[4][64];
    __shared__ float sc[64], sh[64];
    const int y0 = blockIdx.x * 2, b = blockIdx.y;
    const int tid = threadIdx.x;

    {
        int c = tid & 63, gp = tid >> 6;
        float s = 0.f, q = 0.f;
#pragma unroll 8
        for (int i = 0; i < 32; i++) {
            int blk = gp * 32 + i;
            s += g_p1s[blk * 64 + c];
            q += g_p1q[blk * 64 + c];
        }
        ps[gp][c] = s; pq[gp][c] = q;
    }
    __syncthreads();
    if (tid < 64) {
        float s = ps[0][tid] + ps[1][tid] + ps[2][tid] + ps[3][tid];
        float q = pq[0][tid] + pq[1][tid] + pq[2][tid] + pq[3][tid];
        const float inv = 1.f / 32768.f;
        float m = s * inv, var = fmaf(-m, m, q * inv);
        float k = gam[tid] * rsqrtf(var + EPS);
        sc[tid] = k; sh[tid] = bet[tid] - m * k;
    }

#pragma unroll 1
    for (int ry = 0; ry < 2; ry++) {
        const int y = y0 + ry;
        __syncthreads();
#pragma unroll
        for (int it = 0; it < 4; it++) {
            int idx = it * 256 + tid;
            int c = idx >> 4, x4 = idx & 15;
            float4 v = *(const float4*)&g_t1[((size_t)(b * MID + c) << 12)
                                             + (y << 6) + x4 * 4];
            float z0 = fmaf(v.x, sc[c], sh[c]);
            float z1 = fmaf(v.y, sc[c], sh[c]);
            float z2 = fmaf(v.z, sc[c], sh[c]);
            float z3 = fmaf(v.w, sc[c], sh[c]);
            ts[c][x4 * 4 + 0] = z0 * (1.f / (1.f + __expf(-z0)));
            ts[c][x4 * 4 + 1] = z1 * (1.f / (1.f + __expf(-z1)));
            ts[c][x4 * 4 + 2] = z2 * (1.f / (1.f + __expf(-z2)));
            ts[c][x4 * 4 + 3] = z3 * (1.f / (1.f + __expf(-z3)));
        }
        __syncthreads();
        const size_t rowbase = (size_t)((b << 6) + y) << 12;
        uint32_t* dH = (uint32_t*)(g_aH + rowbase);
        uint32_t* dL = (uint32_t*)(g_aL + rowbase);
#pragma unroll
        for (int it = 0; it < 8; it++) {
            int idx = it * 256 + tid;
            int xx = idx >> 5, cp = idx & 31;
            float v0 = ts[2 * cp][xx], v1 = ts[2 * cp + 1][xx];
            u16 h0 = bfbits(v0), h1 = bfbits(v1);
            u16 l0 = bfbits(v0 - bf2f(h0)), l1 = bfbits(v1 - bf2f(h1));
            dH[xx * 32 + cp] = (uint32_t)h0 | ((uint32_t)h1 << 16);
            dL[xx * 32 + cp] = (uint32_t)l0 | ((uint32_t)l1 << 16);
        }
    }
}

// ---------------------------------------------------------------------------
// conv3 (R16 structure; mma chain interleaved across mt within each nt).
// ---------------------------------------------------------------------------
#define ABYTES 42240
#define C3_SMEM (ABYTES + 20480 + 256)

__global__ __launch_bounds__(256) void k_conv3mma() {
    extern __shared__ __align__(16) char smc[];
    __shared__ float sAcc[128], qAcc[128];
    const uint32_t sb = smem_u32(smc);
    const int tid = threadIdx.x;
    const int tile = blockIdx.x, b = blockIdx.y;
    const int p0 = tile * 128;
    const int lane = tid & 31, wid = tid >> 5;
    const int g = lane >> 2, tg = lane & 3;
    const int wm = wid >> 1, wn = wid & 1;
    const int m0 = wm * 32, n0 = wn * 64;

    if (tid < 128) { sAcc[tid] = 0.f; qAcc[tid] = 0.f; }

    float acc[2][8][4];
#pragma unroll
    for (int mt = 0; mt < 2; mt++)
#pragma unroll
        for (int nt = 0; nt < 8; nt++)
#pragma unroll
            for (int j = 0; j < 4; j++) acc[mt][nt][j] = 0.f;

    uint32_t aoffm[2];
#pragma unroll
    for (int mt = 0; mt < 2; mt++) {
        int pxl = m0 + mt * 16 + (lane & 15);
        int ty = pxl >> 6, xx = pxl & 63;
        aoffm[mt] = (uint32_t)(((ty + 1) * 66 + xx + 1) * 80) + ((lane >> 4) << 4);
    }
    const uint32_t blane = (uint32_t)((n0 + (lane & 7)) * 80) + (((lane >> 3) & 3) << 4);

#pragma unroll 1
    for (int half = 0; half < 2; half++) {
        __syncthreads();
        for (int idx = tid; idx < 2112; idx += 256) {
            int arr = idx / 1056;
            int j = idx - arr * 1056;
            int px = j >> 2, u = j & 3;
            int r = px / 66, cc = px - r * 66;
            int gy = tile * 2 - 1 + r, gx = cc - 1;
            float4 v = make_float4(0.f, 0.f, 0.f, 0.f);
            if ((unsigned)gy < 64u && (unsigned)gx < 64u) {
                const u16* src = (arr ? g_aL : g_aH) +
                    ((size_t)(b << 12) + (gy << 6) + gx) * 64 + half * 32 + u * 8;
                v = *(const float4*)src;
            }
            *(float4*)(smc + arr * 21120 + px * 80 + u * 16) = v;
        }

#pragma unroll 1
        for (int tap = 0; tap < 9; tap++) {
            if (tap > 0) __syncthreads();
            {
                const int chunk = tap * 2 + half;
#pragma unroll
                for (int it = 0; it < 4; it++) {
                    int j = it * 256 + tid;
                    int arr = j >> 9, jb = j & 511;
                    int oc = jb >> 2, u = jb & 3;
                    const u16* src = (arr ? g_wL : g_wH) + (chunk << 12) + oc * 32 + u * 8;
                    *(float4*)(smc + ABYTES + arr * 10240 + oc * 80 + u * 16) =
                        *(const float4*)src;
                }
            }
            __syncthreads();

            const int dyq = tap / 3;
            const int tapoff = ((dyq - 1) * 66 + (tap - 3 * dyq - 1)) * 80;

#pragma unroll
            for (int ks = 0; ks < 2; ks++) {
                const uint32_t ko = ks * 32;
                uint32_t aH[2][4], aL[2][4];
#pragma unroll
                for (int mt = 0; mt < 2; mt++) {
                    uint32_t a = sb + aoffm[mt] + tapoff + ko;
                    lm4(aH[mt][0], aH[mt][1], aH[mt][2], aH[mt][3], a);
                    lm4(aL[mt][0], aL[mt][1], aL[mt][2], aL[mt][3], a + 21120);
                }
#pragma unroll
                for (int nt = 0; nt < 8; nt++) {
                    uint32_t ba = sb + ABYTES + blane + nt * 640 + ko;
                    uint32_t bH0, bH1, bL0, bL1;
                    lm2(bH0, bH1, ba);
                    lm2(bL0, bL1, ba + 10240);
                    // pass-major over the 3-mma chain: same-acc distance = 2
#pragma unroll
                    for (int mt = 0; mt < 2; mt++)
                        mmabf(acc[mt][nt][0], acc[mt][nt][1], acc[mt][nt][2], acc[mt][nt][3],
                              aH[mt][0], aH[mt][1], aH[mt][2], aH[mt][3], bH0, bH1);
#pragma unroll
                    for (int mt = 0; mt < 2; mt++)
                        mmabf(acc[mt][nt][0], acc[mt][nt][1], acc[mt][nt][2], acc[mt][nt][3],
                              aH[mt][0], aH[mt][1], aH[mt][2], aH[mt][3], bL0, bL1);
#pragma unroll
                    for (int mt = 0; mt < 2; mt++)
                        mmabf(acc[mt][nt][0], acc[mt][nt][1], acc[mt][nt][2], acc[mt][nt][3],
                              aL[mt][0], aL[mt][1], aL[mt][2], aL[mt][3], bH0, bH1);
                }
            }
        }
        __syncthreads();
    }

    // epilogue: store + BN2 partials
#pragma unroll
    for (int mt = 0; mt < 2; mt++) {
#pragma unroll
        for (int nt = 0; nt < 8; nt++) {
            int oc0 = n0 + nt * 8 + 2 * tg;
            int pxl = m0 + mt * 16 + g;
            float c0 = acc[mt][nt][0], c1 = acc[mt][nt][1];
            float c2 = acc[mt][nt][2], c3 = acc[mt][nt][3];
            if (oc0 < 100) {
                size_t ob = ((size_t)(b * OC2 + oc0) << 12) + p0 + pxl;
                g_t2[ob] = c0;
                g_t2[ob + 8] = c2;
                if (oc0 + 1 < 100) {
                    g_t2[ob + HW] = c1;
                    g_t2[ob + HW + 8] = c3;
                }
            }
            float s0 = c0 + c2, q0 = fmaf(c0, c0, c2 * c2);
            float s1 = c1 + c3, q1 = fmaf(c1, c1, c3 * c3);
#pragma unroll
            for (int o = 16; o >= 4; o >>= 1) {
                s0 += __shfl_down_sync(0xFFFFFFFFu, s0, o);
                q0 += __shfl_down_sync(0xFFFFFFFFu, q0, o);
                s1 += __shfl_down_sync(0xFFFFFFFFu, s1, o);
                q1 += __shfl_down_sync(0xFFFFFFFFu, q1, o);
            }
            if (lane < 4 && oc0 < 100) {
                atomicAdd(&sAcc[oc0], s0);
                atomicAdd(&qAcc[oc0], q0);
                if (oc0 + 1 < 100) {
                    atomicAdd(&sAcc[oc0 + 1], s1);
                    atomicAdd(&qAcc[oc0 + 1], q1);
                }
            }
        }
    }
    __syncthreads();
    if (tid < 100) {
        int blk = b * 32 + tile;
        g_p2s[blk * 100 + tid] = sAcc[tid];
        g_p2q[blk * 100 + tid] = qAcc[tid];
    }
}

__global__ void k_fin2(const float* __restrict__ gam, const float* __restrict__ bet) {
    const int oc = blockIdx.x, t = threadIdx.x;
    float s = g_p2s[t * 100 + oc], q = g_p2q[t * 100 + oc];
#pragma unroll
    for (int o = 16; o; o >>= 1) {
        s += __shfl_down_sync(0xFFFFFFFFu, s, o);
        q += __shfl_down_sync(0xFFFFFFFFu, q, o);
    }
    __shared__ float ss[8], qq[8];
    if ((t & 31) == 0) { ss[t >> 5] = s; qq[t >> 5] = q; }
    __syncthreads();
    if (t == 0) {
        s = 0.f; q = 0.f;
#pragma unroll
        for (int i = 0; i < 8; i++) { s += ss[i]; q += qq[i]; }
        const float inv = 1.f / 32768.f;
        float m = s * inv, var = fmaf(-m, m, q * inv);
        float k = gam[oc] * rsqrtf(var + EPS);
        g_sc2[oc] = k; g_sh2[oc] = bet[oc] - m * k;
    }
}

// ---------------------------------------------------------------------------
// reassembly: RPOS 144 (bank-conflict-free LDS.128: 4qx+9s4 bijective mod 32)
// ---------------------------------------------------------------------------
#define RPOS 144
#define REASM_SMEM ((144 * RPOS + 256 * 25) * 4)

__global__ __launch_bounds__(256, 2) void k_reasm(const float* __restrict__ x,
                                                  float* __restrict__ out) {
    extern __shared__ float sm[];
    float* srcs = sm;
    float* wgt = sm + 144 * RPOS;

    const int b = blockIdx.y;
    const int ti0 = (blockIdx.x >> 3) << 4;
    const int tj0 = (blockIdx.x & 7) << 4;
    const int tid = threadIdx.x;
    const int sy0 = (ti0 >> 1) - 2;
    const int sx0 = (tj0 >> 1) - 2;

#pragma unroll 4
    for (int it = 0; it < 72; it++) {
        int idx = tid + it * 256;
        int c = idx / 144;
        int pos = idx - c * 144;
        int yy = pos / 12;
        int xx = pos - yy * 12;
        int gy = sy0 + yy, gx = sx0 + xx;
        float v = 0.f;
        if ((unsigned)gy < 64u && (unsigned)gx < 64u)
            v = x[((size_t)(b * CIN + c) << 12) + (gy << 6) + gx];
        int p = c >> 1;
        srcs[pos * RPOS + (p >> 4) * 36 + (p & 15) * 2 + (c & 1)] = v;
    }

    {
        int py = tid >> 4, px = tid & 15;
        int gi = ti0 + py, gj = tj0 + px;
        int y0 = gi >> 1, x0 = gj >> 1;
        int sub = ((gi & 1) << 1) | (gj & 1);
        float l[25];
        float mx = -1e30f;
#pragma unroll
        for (int k = 0; k < 25; k++) {
            int ch = (k << 2) + sub;
            float v = fmaf(g_t2[((size_t)(b * OC2 + ch) << 12) + (y0 << 6) + x0],
                           g_sc2[ch], g_sh2[ch]);
            l[k] = v;
            mx = fmaxf(mx, v);
        }
        float s = 0.f;
#pragma unroll
        for (int k = 0; k < 25; k++) { l[k] = __expf(l[k] - mx); s += l[k]; }
        float inv = 1.f / s;
#pragma unroll
        for (int k = 0; k < 25; k++) wgt[tid * 25 + k] = l[k] * inv;
    }
    __syncthreads();

    const int s4 = tid & 3;
    const int quad = tid >> 2;
    const int qy = quad >> 3, qx = quad & 7;
    const int posb = qy * 12 + qx;
    const float* wp0 = &wgt[(2 * qy * 16 + 2 * qx) * 25];
    const int gi0 = ti0 + 2 * qy;
    const int gj = tj0 + 2 * qx;

#pragma unroll 1
    for (int g = 0; g < 2; g++) {
        u64 a[2][2][8];
#pragma unroll
        for (int di = 0; di < 2; di++)
#pragma unroll
            for (int dj = 0; dj < 2; dj++)
#pragma unroll
                for (int j = 0; j < 8; j++) a[di][dj][j] = 0ull;

#pragma unroll 1
        for (int dy = 0; dy < 5; dy++) {
#pragma unroll
            for (int dx = 0; dx < 5; dx++) {
                int k = dy * 5 + dx;
                float w00 = wp0[k], w01 = wp0[25 + k];
                float w10 = wp0[400 + k], w11 = wp0[425 + k];
                u64 W00 = pk(w00, w00), W01 = pk(w01, w01);
                u64 W10 = pk(w10, w10), W11 = pk(w11, w11);
                const ulonglong2* r = (const ulonglong2*)(
                    srcs + (posb + dy * 12 + dx) * RPOS + s4 * 36 + g * 16);
                ulonglong2 q0 = r[0], q1 = r[1], q2 = r[2], q3 = r[3];
                u64 sv[8] = {q0.x, q0.y, q1.x, q1.y, q2.x, q2.y, q3.x, q3.y};
#pragma unroll
                for (int j = 0; j < 8; j++) {
                    fma2(a[0][0][j], W00, sv[j]);
                    fma2(a[0][1][j], W01, sv[j]);
                    fma2(a[1][0][j], W10, sv[j]);
                    fma2(a[1][1][j], W11, sv[j]);
                }
            }
        }

#pragma unroll
        for (int j = 0; j < 8; j++) {
            int p = s4 * 16 + g * 8 + j;
            int c = 2 * p;
#pragma unroll
            for (int di = 0; di < 2; di++) {
                float e0, h0, e1, h1;
                unpk(a[di][0][j], e0, h0);
                unpk(a[di][1][j], e1, h1);
                size_t ob = (((size_t)(b * CIN + c) << 7) + gi0 + di) * 128 + gj;
                *(float2*)&out[ob] = make_float2(e0, e1);
                *(float2*)&out[ob + 16384] = make_float2(h0, h1);
            }
        }
    }
}

// ---------------------------------------------------------------------------
extern "C" void kernel_launch(void* const* d_in, const int* in_sizes, int n_in,
                              void* d_out, int out_size) {
    const float* x      = (const float*)d_in[0];
    const float* comp_w = (const float*)d_in[1];
    const float* comp_g = (const float*)d_in[2];
    const float* comp_b = (const float*)d_in[3];
    const float* enc_w  = (const float*)d_in[4];
    const float* enc_g  = (const float*)d_in[5];
    const float* enc_b  = (const float*)d_in[6];
    float* out = (float*)d_out;

    cudaFuncSetAttribute(k_conv3mma, cudaFuncAttributeMaxDynamicSharedMemorySize, C3_SMEM);
    cudaFuncSetAttribute(k_reasm, cudaFuncAttributeMaxDynamicSharedMemorySize, REASM_SMEM);

    k_prep<<<320, 256>>>(comp_w, enc_w);                 // 0
    k_conv1<<<dim3(16, B), 256>>>(x);                    // 1
    k_act<<<dim3(32, B), 256>>>(comp_g, comp_b);         // 2
    k_conv3mma<<<dim3(32, B), 256, C3_SMEM>>>();         // 3  <- ncu slot
    k_fin2<<<OC2, 256>>>(enc_g, enc_b);                  // 4
    k_reasm<<<dim3(64, B), 256, REASM_SMEM>>>(x, out);   // 5
}